// round 4
// baseline (speedup 1.0000x reference)
#include <cuda_runtime.h>
#include <math.h>

// Problem constants
#define BATCH 64
#define TT    512
#define FF    1024
#define HH    1024
#define G4    4096   // 4*H
#define NCTA  128    // persistent CTAs (< 148 SMs -> all co-resident)

// ---------------- scratch (static device memory; no allocations) ------------
static __device__ float g_xg[(size_t)BATCH * TT * G4];   // x @ Wx for all t
static __device__ unsigned g_bar_count;                  // grid barrier arrive count
static __device__ volatile unsigned g_bar_gen;           // grid barrier generation

// ============================================================================
// Phase 1: xg[b*T+t, 0:4096] = x[b*T+t, 0:1024] @ Wx[1024, 4096]
// Tile: 128 rows x 64 cols, K-chunk 32. 256 threads, microtile 8x4 (stride-16).
// (validated in R2 run)
// ============================================================================
__global__ __launch_bounds__(256, 3)
void gemm_xw_kernel(const float* __restrict__ x, const float* __restrict__ Wx)
{
    __shared__ float sA[128][36];   // [row][k], padded
    __shared__ float sB[32][68];    // [k][col], padded

    const int tid = threadIdx.x;
    const int row0 = blockIdx.y * 128;
    const int col0 = blockIdx.x * 64;
    const int rg = tid >> 4;   // 0..15  (rows rg, rg+16, ..., rg+112)
    const int cg = tid & 15;   // 0..15  (cols cg, cg+16, cg+32, cg+48)

    float acc[8][4];
#pragma unroll
    for (int m = 0; m < 8; m++)
#pragma unroll
        for (int n = 0; n < 4; n++) acc[m][n] = 0.f;

    for (int k0 = 0; k0 < FF; k0 += 32) {
#pragma unroll
        for (int i = 0; i < 4; i++) {
            int fi = tid + i * 256;
            int r  = fi >> 3;
            int kb = fi & 7;
            float4 v = *(const float4*)&x[(size_t)(row0 + r) * FF + k0 + kb * 4];
            *(float4*)&sA[r][kb * 4] = v;
        }
#pragma unroll
        for (int i = 0; i < 2; i++) {
            int fi = tid + i * 256;
            int kk = fi >> 4;
            int cf = fi & 15;
            float4 v = *(const float4*)&Wx[(size_t)(k0 + kk) * G4 + col0 + cf * 4];
            *(float4*)&sB[kk][cf * 4] = v;
        }
        __syncthreads();

#pragma unroll 8
        for (int kk = 0; kk < 32; kk++) {
            float a[8], b[4];
#pragma unroll
            for (int m = 0; m < 8; m++) a[m] = sA[rg + 16 * m][kk];
#pragma unroll
            for (int n = 0; n < 4; n++) b[n] = sB[kk][cg + 16 * n];
#pragma unroll
            for (int m = 0; m < 8; m++)
#pragma unroll
                for (int n = 0; n < 4; n++) acc[m][n] += a[m] * b[n];
        }
        __syncthreads();
    }

#pragma unroll
    for (int m = 0; m < 8; m++)
#pragma unroll
        for (int n = 0; n < 4; n++)
            g_xg[(size_t)(row0 + rg + 16 * m) * G4 + col0 + cg + 16 * n] = acc[m][n];
}

// ============================================================================
// Phase 2: persistent LSTM recurrence. 128 CTAs x 256 threads.
// CTA `blk` owns h-columns [blk*8, blk*8+8) for ALL gates and ALL 64 batches.
// Per step: z-tile (64 x 32 gate-cols) = h_{t-1} @ Wh slice (in registers),
// then gate pointwise in-register (c also register-resident), write h to out,
// one grid barrier.
// ============================================================================
__device__ __forceinline__ float sigmoidf_(float v) { return 1.f / (1.f + expf(-v)); }

__global__ __launch_bounds__(256, 1)
void lstm_persistent_kernel(const float* __restrict__ Wh,
                            const float* __restrict__ bias,
                            float* __restrict__ out)
{
    __shared__ float sH[64][36];    // [batch][k-chunk], padded
    __shared__ float sW[32][36];    // [k][localcol: gate*8 + hc], padded

    const int tid = threadIdx.x;
    const int blk = blockIdx.x;       // 0..127
    const int rg  = tid >> 3;         // 0..31 -> batch rows rg, rg+32
    const int cg  = tid & 7;          // 0..7  -> h-col within block
    const int hc  = blk * 8 + cg;     // global h column

    const float bi = bias[hc];
    const float bf = bias[1024 + hc];
    const float bg = bias[2048 + hc];
    const float bo = bias[3072 + hc];

    float c0 = 0.f, c1 = 0.f;         // register-resident cell state

    // staging decomposition (fixed per thread)
    const int hr0 = tid >> 3;                 // 0..31
    const int hk0 = (tid & 7) * 4;            // 0,4,...,28
    const int hr1 = hr0 + 32;                 // 32..63
    const int wkk   = tid >> 3;               // 0..31
    const int wgate = (tid & 7) >> 1;         // 0..3
    const int wcol4 = (tid & 1) * 4;          // 0 or 4
    const size_t w_off = (size_t)wgate * 1024 + (size_t)blk * 8 + wcol4;

    for (int t = 0; t < TT; t++) {
        // prefetch xg contributions for this thread's 2 rows x 4 gates
        const float* xg0 = g_xg + ((size_t)rg * TT + t) * G4 + hc;
        const float* xg1 = g_xg + ((size_t)(rg + 32) * TT + t) * G4 + hc;
        float x00 = xg0[0], x01 = xg0[1024], x02 = xg0[2048], x03 = xg0[3072];
        float x10 = xg1[0], x11 = xg1[1024], x12 = xg1[2048], x13 = xg1[3072];

        float acc00 = 0.f, acc01 = 0.f, acc02 = 0.f, acc03 = 0.f;
        float acc10 = 0.f, acc11 = 0.f, acc12 = 0.f, acc13 = 0.f;

        if (t > 0) {
            const float* hbase = out + (size_t)(t - 1) * HH;  // h[r][k] = hbase[r*T*H + k]

            // register double-buffer: preload chunk 0
            float4 hA = *(const float4*)&hbase[(size_t)hr0 * (TT * HH) + hk0];
            float4 hB = *(const float4*)&hbase[(size_t)hr1 * (TT * HH) + hk0];
            float4 wA = *(const float4*)&Wh[(size_t)wkk * G4 + w_off];

            for (int k0 = 0; k0 < FF; k0 += 32) {
                *(float4*)&sH[hr0][hk0] = hA;
                *(float4*)&sH[hr1][hk0] = hB;
                *(float4*)&sW[wkk][wgate * 8 + wcol4] = wA;
                __syncthreads();

                int kn = k0 + 32;
                if (kn < FF) {
                    hA = *(const float4*)&hbase[(size_t)hr0 * (TT * HH) + kn + hk0];
                    hB = *(const float4*)&hbase[(size_t)hr1 * (TT * HH) + kn + hk0];
                    wA = *(const float4*)&Wh[(size_t)(kn + wkk) * G4 + w_off];
                }

#pragma unroll
                for (int kk = 0; kk < 32; kk++) {
                    float a0 = sH[rg][kk];
                    float a1 = sH[rg + 32][kk];
                    float w0 = sW[kk][cg];
                    float w1 = sW[kk][8 + cg];
                    float w2 = sW[kk][16 + cg];
                    float w3 = sW[kk][24 + cg];
                    acc00 += a0 * w0; acc01 += a0 * w1;
                    acc02 += a0 * w2; acc03 += a0 * w3;
                    acc10 += a1 * w0; acc11 += a1 * w1;
                    acc12 += a1 * w2; acc13 += a1 * w3;
                }
                __syncthreads();
            }
        }

        // ---- pointwise gates (in registers) ----
        {
            float zi = x00 + bi + acc00;
            float zf = x01 + bf + acc01;
            float zg = x02 + bg + acc02;
            float zo = x03 + bo + acc03;
            float cn = sigmoidf_(zf) * c0 + sigmoidf_(zi) * tanhf(zg);
            float hn = sigmoidf_(zo) * tanhf(cn);
            c0 = cn;
            out[((size_t)rg * TT + t) * HH + hc] = hn;

            zi = x10 + bi + acc10;
            zf = x11 + bf + acc11;
            zg = x12 + bg + acc12;
            zo = x13 + bo + acc13;
            cn = sigmoidf_(zf) * c1 + sigmoidf_(zi) * tanhf(zg);
            hn = sigmoidf_(zo) * tanhf(cn);
            c1 = cn;
            out[((size_t)(rg + 32) * TT + t) * HH + hc] = hn;
        }

        // ---- grid barrier (sense-reversal; state returns clean each barrier) ----
        __threadfence();        // make h writes visible at gpu scope
        __syncthreads();
        if (tid == 0) {
            unsigned gen = g_bar_gen;
            if (atomicAdd(&g_bar_count, 1) == NCTA - 1) {
                g_bar_count = 0;
                __threadfence();
                g_bar_gen = gen + 1;       // release
            } else {
                while (g_bar_gen == gen) { __nanosleep(64); }
            }
        }
        __syncthreads();
    }
}

// ============================================================================
// Launch: exactly 2 graph nodes.
// ============================================================================
extern "C" void kernel_launch(void* const* d_in, const int* in_sizes, int n_in,
                              void* d_out, int out_size)
{
    const float* x  = (const float*)d_in[0];   // [64, 512, 1024]
    const float* Wx = (const float*)d_in[1];   // [1024, 4096]
    const float* Wh = (const float*)d_in[2];   // [1024, 4096]
    const float* b  = (const float*)d_in[3];   // [4096]
    float* out = (float*)d_out;                // [64, 512, 1024]

    // Phase 1: xg = x @ Wx for all timesteps
    {
        dim3 grid(G4 / 64, (BATCH * TT) / 128);   // (64, 256)
        gemm_xw_kernel<<<grid, 256>>>(x, Wx);
    }

    // Phase 2: persistent recurrence (single launch)
    lstm_persistent_kernel<<<NCTA, 256>>>(Wh, b, out);
}

// round 7
// speedup vs baseline: 1.2033x; 1.2033x over previous
#include <cuda_runtime.h>
#include <cuda_bf16.h>
#include <math.h>
#include <cstdint>

// Problem constants
#define BATCH 64
#define TT    512
#define FF    1024
#define HH    1024
#define G4    4096          // 4*H
#define NCTA  128           // persistent CTAs for phase 2
#define MROWS (BATCH * TT)  // 32768 rows of xg

// ---------------- scratch (static device memory; no allocations) ------------
static __device__ float          g_xg[(size_t)MROWS * G4];    // x @ Wx, fp32
static __device__ __nv_bfloat16  g_xhi[(size_t)MROWS * FF];   // [m][k]
static __device__ __nv_bfloat16  g_xlo[(size_t)MROWS * FF];
static __device__ __nv_bfloat16  g_wthi[(size_t)G4 * FF];     // WxT [n][k]
static __device__ __nv_bfloat16  g_wtlo[(size_t)G4 * FF];
static __device__ unsigned       g_bar_count;
static __device__ volatile unsigned g_bar_gen;

// ======================= baseline-PTX MMA helpers ===========================
__device__ __forceinline__ uint32_t smem_u32(const void* p) {
    uint32_t a;
    asm("{ .reg .u64 t; cvta.to.shared.u64 t, %1; cvt.u32.u64 %0, t; }"
        : "=r"(a) : "l"(p));
    return a;
}
__device__ __forceinline__ void ldsm_x4(uint32_t& r0, uint32_t& r1,
                                        uint32_t& r2, uint32_t& r3, uint32_t addr) {
    asm volatile("ldmatrix.sync.aligned.m8n8.x4.shared.b16 {%0,%1,%2,%3}, [%4];"
                 : "=r"(r0), "=r"(r1), "=r"(r2), "=r"(r3) : "r"(addr));
}
__device__ __forceinline__ void mma16816(float* d, const uint32_t* a, const uint32_t* b) {
    asm volatile(
        "mma.sync.aligned.m16n8k16.row.col.f32.bf16.bf16.f32 "
        "{%0,%1,%2,%3}, {%4,%5,%6,%7}, {%8,%9}, {%0,%1,%2,%3};"
        : "+f"(d[0]), "+f"(d[1]), "+f"(d[2]), "+f"(d[3])
        : "r"(a[0]), "r"(a[1]), "r"(a[2]), "r"(a[3]), "r"(b[0]), "r"(b[1]));
}
// SW64 swizzle for 64B rows: seg' = seg ^ ((row>>1)&3); addr = row*64 + seg'*16
__device__ __forceinline__ uint32_t sw64(int row, int seg) {
    return (uint32_t)(row * 64 + ((seg ^ ((row >> 1) & 3)) << 4));
}

// ============================================================================
// Conversions: fp32 -> bf16 hi/lo pairs
// ============================================================================
__global__ __launch_bounds__(256)
void convert_x_kernel(const float* __restrict__ x)
{
    size_t i = (size_t)blockIdx.x * blockDim.x + threadIdx.x;  // one per 4 elems
    float4 v = ((const float4*)x)[i];
    float vv[4] = {v.x, v.y, v.z, v.w};
    __nv_bfloat16 hi[4], lo[4];
#pragma unroll
    for (int j = 0; j < 4; j++) {
        hi[j] = __float2bfloat16(vv[j]);
        lo[j] = __float2bfloat16(vv[j] - __bfloat162float(hi[j]));
    }
    __nv_bfloat162* xh = (__nv_bfloat162*)g_xhi;
    __nv_bfloat162* xl = (__nv_bfloat162*)g_xlo;
    xh[2 * i]     = __halves2bfloat162(hi[0], hi[1]);
    xh[2 * i + 1] = __halves2bfloat162(hi[2], hi[3]);
    xl[2 * i]     = __halves2bfloat162(lo[0], lo[1]);
    xl[2 * i + 1] = __halves2bfloat162(lo[2], lo[3]);
}

__global__ __launch_bounds__(256)
void convert_wt_kernel(const float* __restrict__ Wx)
{
    size_t idx = (size_t)blockIdx.x * blockDim.x + threadIdx.x;
    int k = (int)(idx >> 12);
    int n = (int)(idx & 4095);
    float v = Wx[idx];
    __nv_bfloat16 hi = __float2bfloat16(v);
    __nv_bfloat16 lo = __float2bfloat16(v - __bfloat162float(hi));
    g_wthi[(size_t)n * FF + k] = hi;
    g_wtlo[(size_t)n * FF + k] = lo;
}

// ============================================================================
// Phase 1 (warp MMA): xg = x @ Wx via bf16 hi/lo (3 products), fp32 accum.
// CTA 128x128, KC=32, 8 warps (warp tile 32x64), double-buffered SMEM.
// SMEM tiles (per buffer): Ahi 8K | Alo 8K | Bhi 8K | Blo 8K = 32 KB.
// ============================================================================
#define KC        32
#define TILE_SB   8192
#define STAGE_SB  (4 * TILE_SB)
#define SMEM_DYN  (2 * STAGE_SB + 1024)

__global__ __launch_bounds__(256)
void gemm_mma_kernel()
{
    extern __shared__ char smem_raw[];
    char* smem = (char*)(((uintptr_t)smem_raw + 1023) & ~(uintptr_t)1023);
    const uint32_t sb = smem_u32(smem);

    const int tid = threadIdx.x;
    const int wid = tid >> 5;
    const int lane = tid & 31;
    const int wm = wid & 3;            // warp m: 32*wm
    const int wn = wid >> 2;           // warp n: 64*wn
    const int col0 = blockIdx.x * 128; // N block (fast dim)
    const int row0 = blockIdx.y * 128; // M block

    // staging indices (8 float4 per thread per chunk: 2 per tile x 4 tiles)
    const int srow0 = tid >> 2;            // 0..63
    const int sseg  = tid & 3;             // 0..3
    const int srow1 = srow0 + 64;          // 64..127

    float acc[2][8][4];
#pragma unroll
    for (int i = 0; i < 2; i++)
#pragma unroll
        for (int j = 0; j < 8; j++)
#pragma unroll
            for (int q = 0; q < 4; q++) acc[i][j][q] = 0.f;

    // prefetch chunk 0
    float4 pAh0, pAh1, pAl0, pAl1, pBh0, pBh1, pBl0, pBl1;
    {
        const size_t a0 = (size_t)(row0 + srow0) * FF + sseg * 8;
        const size_t a1 = (size_t)(row0 + srow1) * FF + sseg * 8;
        const size_t b0 = (size_t)(col0 + srow0) * FF + sseg * 8;
        const size_t b1 = (size_t)(col0 + srow1) * FF + sseg * 8;
        pAh0 = *(const float4*)(g_xhi + a0);  pAh1 = *(const float4*)(g_xhi + a1);
        pAl0 = *(const float4*)(g_xlo + a0);  pAl1 = *(const float4*)(g_xlo + a1);
        pBh0 = *(const float4*)(g_wthi + b0); pBh1 = *(const float4*)(g_wthi + b1);
        pBl0 = *(const float4*)(g_wtlo + b0); pBl1 = *(const float4*)(g_wtlo + b1);
    }

    for (int c = 0; c < FF / KC; c++) {       // 32 chunks
        const uint32_t stg = (uint32_t)(c & 1) * STAGE_SB;
        // store staged regs
        const uint32_t s0 = sw64(srow0, sseg);
        const uint32_t s1 = sw64(srow1, sseg);
        *(float4*)(smem + stg + 0 * TILE_SB + s0) = pAh0;
        *(float4*)(smem + stg + 0 * TILE_SB + s1) = pAh1;
        *(float4*)(smem + stg + 1 * TILE_SB + s0) = pAl0;
        *(float4*)(smem + stg + 1 * TILE_SB + s1) = pAl1;
        *(float4*)(smem + stg + 2 * TILE_SB + s0) = pBh0;
        *(float4*)(smem + stg + 2 * TILE_SB + s1) = pBh1;
        *(float4*)(smem + stg + 3 * TILE_SB + s0) = pBl0;
        *(float4*)(smem + stg + 3 * TILE_SB + s1) = pBl1;
        __syncthreads();

        // prefetch next chunk
        if (c + 1 < FF / KC) {
            const int kn = (c + 1) * KC;
            const size_t a0 = (size_t)(row0 + srow0) * FF + kn + sseg * 8;
            const size_t a1 = (size_t)(row0 + srow1) * FF + kn + sseg * 8;
            const size_t b0 = (size_t)(col0 + srow0) * FF + kn + sseg * 8;
            const size_t b1 = (size_t)(col0 + srow1) * FF + kn + sseg * 8;
            pAh0 = *(const float4*)(g_xhi + a0);  pAh1 = *(const float4*)(g_xhi + a1);
            pAl0 = *(const float4*)(g_xlo + a0);  pAl1 = *(const float4*)(g_xlo + a1);
            pBh0 = *(const float4*)(g_wthi + b0); pBh1 = *(const float4*)(g_wthi + b1);
            pBl0 = *(const float4*)(g_wtlo + b0); pBl1 = *(const float4*)(g_wtlo + b1);
        }

        // compute 2 k16 halves from this buffer
#pragma unroll
        for (int kk = 0; kk < 2; kk++) {
            // ldmatrix pointers: row = base + lane%16, seg = 2*kk + lane/16
            const int lrow = lane & 15;
            const int lseg = 2 * kk + (lane >> 4);

            uint32_t ah[2][4], al[2][4];
#pragma unroll
            for (int i = 0; i < 2; i++) {
                int r = 32 * wm + 16 * i + lrow;
                uint32_t ad = sb + stg + 0 * TILE_SB + sw64(r, lseg);
                ldsm_x4(ah[i][0], ah[i][1], ah[i][2], ah[i][3], ad);
                ad = sb + stg + 1 * TILE_SB + sw64(r, lseg);
                ldsm_x4(al[i][0], al[i][1], al[i][2], al[i][3], ad);
            }
            uint32_t bh[8][2], bl[8][2];
#pragma unroll
            for (int jj = 0; jj < 4; jj++) {   // each x4 covers two n8 frags
                int r = 64 * wn + 16 * jj + lrow;
                uint32_t r0, r1, r2, r3;
                uint32_t bd = sb + stg + 2 * TILE_SB + sw64(r, lseg);
                ldsm_x4(r0, r1, r2, r3, bd);
                bh[2 * jj][0] = r0; bh[2 * jj][1] = r2;      // mat0/mat2 -> nfrag even
                bh[2 * jj + 1][0] = r1; bh[2 * jj + 1][1] = r3;
                bd = sb + stg + 3 * TILE_SB + sw64(r, lseg);
                ldsm_x4(r0, r1, r2, r3, bd);
                bl[2 * jj][0] = r0; bl[2 * jj][1] = r2;
                bl[2 * jj + 1][0] = r1; bl[2 * jj + 1][1] = r3;
            }
#pragma unroll
            for (int i = 0; i < 2; i++)
#pragma unroll
                for (int j = 0; j < 8; j++) {
                    mma16816(acc[i][j], ah[i], bh[j]);
                    mma16816(acc[i][j], ah[i], bl[j]);
                    mma16816(acc[i][j], al[i], bh[j]);
                }
        }
        __syncthreads();
    }

    // Epilogue: fragment -> g_xg (fp32). c0,c1 = (row, col..col+1); c2,c3 = row+8.
    const int tq = lane >> 2;       // 0..7
    const int tr = lane & 3;        // 0..3
#pragma unroll
    for (int i = 0; i < 2; i++) {
        const int mbase = row0 + 32 * wm + 16 * i;
#pragma unroll
        for (int j = 0; j < 8; j++) {
            const int nbase = col0 + 64 * wn + 8 * j;
            float* p0 = &g_xg[(size_t)(mbase + tq) * G4 + nbase + 2 * tr];
            float* p1 = &g_xg[(size_t)(mbase + tq + 8) * G4 + nbase + 2 * tr];
            p0[0] = acc[i][j][0]; p0[1] = acc[i][j][1];
            p1[0] = acc[i][j][2]; p1[1] = acc[i][j][3];
        }
    }
}

// ============================================================================
// Phase 2: persistent LSTM recurrence (unchanged, validated in R4).
// ============================================================================
__device__ __forceinline__ float sigmoidf_(float v) { return 1.f / (1.f + expf(-v)); }

__global__ __launch_bounds__(256, 1)
void lstm_persistent_kernel(const float* __restrict__ Wh,
                            const float* __restrict__ bias,
                            float* __restrict__ out)
{
    __shared__ float sH[64][36];
    __shared__ float sW[32][36];

    const int tid = threadIdx.x;
    const int blk = blockIdx.x;
    const int rg  = tid >> 3;
    const int cg  = tid & 7;
    const int hc  = blk * 8 + cg;

    const float bi = bias[hc];
    const float bf = bias[1024 + hc];
    const float bg = bias[2048 + hc];
    const float bo = bias[3072 + hc];

    float c0 = 0.f, c1 = 0.f;

    const int hr0 = tid >> 3;
    const int hk0 = (tid & 7) * 4;
    const int hr1 = hr0 + 32;
    const int wkk   = tid >> 3;
    const int wgate = (tid & 7) >> 1;
    const int wcol4 = (tid & 1) * 4;
    const size_t w_off = (size_t)wgate * 1024 + (size_t)blk * 8 + wcol4;

    for (int t = 0; t < TT; t++) {
        const float* xg0 = g_xg + ((size_t)rg * TT + t) * G4 + hc;
        const float* xg1 = g_xg + ((size_t)(rg + 32) * TT + t) * G4 + hc;
        float x00 = xg0[0], x01 = xg0[1024], x02 = xg0[2048], x03 = xg0[3072];
        float x10 = xg1[0], x11 = xg1[1024], x12 = xg1[2048], x13 = xg1[3072];

        float acc00 = 0.f, acc01 = 0.f, acc02 = 0.f, acc03 = 0.f;
        float acc10 = 0.f, acc11 = 0.f, acc12 = 0.f, acc13 = 0.f;

        if (t > 0) {
            const float* hbase = out + (size_t)(t - 1) * HH;

            float4 hA = *(const float4*)&hbase[(size_t)hr0 * (TT * HH) + hk0];
            float4 hB = *(const float4*)&hbase[(size_t)hr1 * (TT * HH) + hk0];
            float4 wA = *(const float4*)&Wh[(size_t)wkk * G4 + w_off];

            for (int k0 = 0; k0 < FF; k0 += 32) {
                *(float4*)&sH[hr0][hk0] = hA;
                *(float4*)&sH[hr1][hk0] = hB;
                *(float4*)&sW[wkk][wgate * 8 + wcol4] = wA;
                __syncthreads();

                int kn = k0 + 32;
                if (kn < FF) {
                    hA = *(const float4*)&hbase[(size_t)hr0 * (TT * HH) + kn + hk0];
                    hB = *(const float4*)&hbase[(size_t)hr1 * (TT * HH) + kn + hk0];
                    wA = *(const float4*)&Wh[(size_t)(kn + wkk) * G4 + w_off];
                }

#pragma unroll
                for (int kk = 0; kk < 32; kk++) {
                    float a0 = sH[rg][kk];
                    float a1 = sH[rg + 32][kk];
                    float w0 = sW[kk][cg];
                    float w1 = sW[kk][8 + cg];
                    float w2 = sW[kk][16 + cg];
                    float w3 = sW[kk][24 + cg];
                    acc00 += a0 * w0; acc01 += a0 * w1;
                    acc02 += a0 * w2; acc03 += a0 * w3;
                    acc10 += a1 * w0; acc11 += a1 * w1;
                    acc12 += a1 * w2; acc13 += a1 * w3;
                }
                __syncthreads();
            }
        }

        {
            float zi = x00 + bi + acc00;
            float zf = x01 + bf + acc01;
            float zg = x02 + bg + acc02;
            float zo = x03 + bo + acc03;
            float cn = sigmoidf_(zf) * c0 + sigmoidf_(zi) * tanhf(zg);
            float hn = sigmoidf_(zo) * tanhf(cn);
            c0 = cn;
            out[((size_t)rg * TT + t) * HH + hc] = hn;

            zi = x10 + bi + acc10;
            zf = x11 + bf + acc11;
            zg = x12 + bg + acc12;
            zo = x13 + bo + acc13;
            cn = sigmoidf_(zf) * c1 + sigmoidf_(zi) * tanhf(zg);
            hn = sigmoidf_(zo) * tanhf(cn);
            c1 = cn;
            out[((size_t)(rg + 32) * TT + t) * HH + hc] = hn;
        }

        __threadfence();
        __syncthreads();
        if (tid == 0) {
            unsigned gen = g_bar_gen;
            if (atomicAdd(&g_bar_count, 1) == NCTA - 1) {
                g_bar_count = 0;
                __threadfence();
                g_bar_gen = gen + 1;
            } else {
                while (g_bar_gen == gen) { __nanosleep(64); }
            }
        }
        __syncthreads();
    }
}

// ============================================================================
// Launch: 4 graph nodes.
// ============================================================================
extern "C" void kernel_launch(void* const* d_in, const int* in_sizes, int n_in,
                              void* d_out, int out_size)
{
    const float* x  = (const float*)d_in[0];   // [64, 512, 1024]
    const float* Wx = (const float*)d_in[1];   // [1024, 4096]
    const float* Wh = (const float*)d_in[2];   // [1024, 4096]
    const float* b  = (const float*)d_in[3];   // [4096]
    float* out = (float*)d_out;                // [64, 512, 1024]

    cudaFuncSetAttribute(gemm_mma_kernel,
                         cudaFuncAttributeMaxDynamicSharedMemorySize, SMEM_DYN);

    // converts
    convert_x_kernel<<<(int)(((size_t)MROWS * FF / 4) / 256), 256>>>(x);
    convert_wt_kernel<<<(int)(((size_t)FF * G4) / 256), 256>>>(Wx);

    // Phase 1: warp-MMA GEMM
    {
        dim3 grid(G4 / 128, MROWS / 128);   // (32, 256)
        gemm_mma_kernel<<<grid, 256, SMEM_DYN>>>();
    }

    // Phase 2: persistent recurrence
    lstm_persistent_kernel<<<NCTA, 256>>>(Wh, b, out);
}

// round 10
// speedup vs baseline: 1.6333x; 1.3574x over previous
#include <cuda_runtime.h>
#include <cuda_bf16.h>
#include <math.h>
#include <cstdint>

// Problem constants
#define BATCH 64
#define TT    512
#define FF    1024
#define HH    1024
#define G4    4096          // 4*H
#define NCTA  128           // persistent CTAs for phase 2
#define MROWS (BATCH * TT)  // 32768 rows of xg
#define KH    128           // phase-2 A staging k-chunk

// ---------------- scratch (static device memory; no allocations) ------------
static __device__ float          g_xg[(size_t)MROWS * G4];    // x @ Wx, fp32
static __device__ __nv_bfloat16  g_xhi[(size_t)MROWS * FF];   // [m][k]
static __device__ __nv_bfloat16  g_xlo[(size_t)MROWS * FF];
static __device__ __nv_bfloat16  g_wthi[(size_t)G4 * FF];     // WxT [n][k]
static __device__ __nv_bfloat16  g_wtlo[(size_t)G4 * FF];
static __device__ __nv_bfloat16  g_whthi[(size_t)G4 * HH];    // WhT [n][k]
static __device__ __nv_bfloat16  g_whtlo[(size_t)G4 * HH];
static __device__ __nv_bfloat16  g_hhi[2][BATCH * HH];        // h hi, by parity
static __device__ __nv_bfloat16  g_hlo[2][BATCH * HH];        // h lo, by parity
static __device__ unsigned       g_bar_count;
static __device__ volatile unsigned g_bar_gen;

// ======================= baseline-PTX MMA helpers ===========================
__device__ __forceinline__ uint32_t smem_u32(const void* p) {
    uint32_t a;
    asm("{ .reg .u64 t; cvta.to.shared.u64 t, %1; cvt.u32.u64 %0, t; }"
        : "=r"(a) : "l"(p));
    return a;
}
__device__ __forceinline__ void ldsm_x4(uint32_t& r0, uint32_t& r1,
                                        uint32_t& r2, uint32_t& r3, uint32_t addr) {
    asm volatile("ldmatrix.sync.aligned.m8n8.x4.shared.b16 {%0,%1,%2,%3}, [%4];"
                 : "=r"(r0), "=r"(r1), "=r"(r2), "=r"(r3) : "r"(addr));
}
__device__ __forceinline__ void mma16816(float* d, const uint32_t* a, const uint32_t* b) {
    asm volatile(
        "mma.sync.aligned.m16n8k16.row.col.f32.bf16.bf16.f32 "
        "{%0,%1,%2,%3}, {%4,%5,%6,%7}, {%8,%9}, {%0,%1,%2,%3};"
        : "+f"(d[0]), "+f"(d[1]), "+f"(d[2]), "+f"(d[3])
        : "r"(a[0]), "r"(a[1]), "r"(a[2]), "r"(a[3]), "r"(b[0]), "r"(b[1]));
}
// SW64 swizzle for 64B rows: seg' = seg ^ ((row>>1)&3); addr = row*64 + seg'*16
__device__ __forceinline__ uint32_t sw64(int row, int seg) {
    return (uint32_t)(row * 64 + ((seg ^ ((row >> 1) & 3)) << 4));
}
// phase-2 swizzles: A rows 256B (16 segs), B rows 2048B (128 segs)
__device__ __forceinline__ uint32_t swA2(int row, int seg) {
    return (uint32_t)((row << 8) + ((seg ^ (row & 7)) << 4));
}
__device__ __forceinline__ uint32_t swB2(int n, int seg) {
    return (uint32_t)((n << 11) + ((seg ^ (n & 7)) << 4));
}

// ============================================================================
// Conversions: fp32 -> bf16 hi/lo pairs
// ============================================================================
__global__ __launch_bounds__(256)
void convert_x_kernel(const float* __restrict__ x)
{
    size_t i = (size_t)blockIdx.x * blockDim.x + threadIdx.x;  // one per 4 elems
    float4 v = ((const float4*)x)[i];
    float vv[4] = {v.x, v.y, v.z, v.w};
    __nv_bfloat16 hi[4], lo[4];
#pragma unroll
    for (int j = 0; j < 4; j++) {
        hi[j] = __float2bfloat16(vv[j]);
        lo[j] = __float2bfloat16(vv[j] - __bfloat162float(hi[j]));
    }
    __nv_bfloat162* xh = (__nv_bfloat162*)g_xhi;
    __nv_bfloat162* xl = (__nv_bfloat162*)g_xlo;
    xh[2 * i]     = __halves2bfloat162(hi[0], hi[1]);
    xh[2 * i + 1] = __halves2bfloat162(hi[2], hi[3]);
    xl[2 * i]     = __halves2bfloat162(lo[0], lo[1]);
    xl[2 * i + 1] = __halves2bfloat162(lo[2], lo[3]);
}

// transpose + split: src [1024 k][4096 n] fp32 -> hi/lo [4096 n][1024 k].
// Destination selected INSIDE device code (device globals are not valid host
// pointers — that was the R9 bug).
__global__ __launch_bounds__(256)
void convert_wt_kernel(const float* __restrict__ src, int which)
{
    __nv_bfloat16* dhi = which ? g_whthi : g_wthi;
    __nv_bfloat16* dlo = which ? g_whtlo : g_wtlo;
    size_t idx = (size_t)blockIdx.x * blockDim.x + threadIdx.x;
    int k = (int)(idx >> 12);
    int n = (int)(idx & 4095);
    float v = src[idx];
    __nv_bfloat16 hi = __float2bfloat16(v);
    __nv_bfloat16 lo = __float2bfloat16(v - __bfloat162float(hi));
    dhi[(size_t)n * FF + k] = hi;
    dlo[(size_t)n * FF + k] = lo;
}

// ============================================================================
// Phase 1 (warp MMA): xg = x @ Wx via bf16 hi/lo (3 products), fp32 accum.
// (validated in R7)
// ============================================================================
#define KC        32
#define TILE_SB   8192
#define STAGE_SB  (4 * TILE_SB)
#define SMEM_DYN  (2 * STAGE_SB + 1024)

__global__ __launch_bounds__(256)
void gemm_mma_kernel()
{
    extern __shared__ char smem_raw[];
    char* smem = (char*)(((uintptr_t)smem_raw + 1023) & ~(uintptr_t)1023);
    const uint32_t sb = smem_u32(smem);

    const int tid = threadIdx.x;
    const int wid = tid >> 5;
    const int lane = tid & 31;
    const int wm = wid & 3;
    const int wn = wid >> 2;
    const int col0 = blockIdx.x * 128;
    const int row0 = blockIdx.y * 128;

    const int srow0 = tid >> 2;
    const int sseg  = tid & 3;
    const int srow1 = srow0 + 64;

    float acc[2][8][4];
#pragma unroll
    for (int i = 0; i < 2; i++)
#pragma unroll
        for (int j = 0; j < 8; j++)
#pragma unroll
            for (int q = 0; q < 4; q++) acc[i][j][q] = 0.f;

    float4 pAh0, pAh1, pAl0, pAl1, pBh0, pBh1, pBl0, pBl1;
    {
        const size_t a0 = (size_t)(row0 + srow0) * FF + sseg * 8;
        const size_t a1 = (size_t)(row0 + srow1) * FF + sseg * 8;
        const size_t b0 = (size_t)(col0 + srow0) * FF + sseg * 8;
        const size_t b1 = (size_t)(col0 + srow1) * FF + sseg * 8;
        pAh0 = *(const float4*)(g_xhi + a0);  pAh1 = *(const float4*)(g_xhi + a1);
        pAl0 = *(const float4*)(g_xlo + a0);  pAl1 = *(const float4*)(g_xlo + a1);
        pBh0 = *(const float4*)(g_wthi + b0); pBh1 = *(const float4*)(g_wthi + b1);
        pBl0 = *(const float4*)(g_wtlo + b0); pBl1 = *(const float4*)(g_wtlo + b1);
    }

    for (int c = 0; c < FF / KC; c++) {
        const uint32_t stg = (uint32_t)(c & 1) * STAGE_SB;
        const uint32_t s0 = sw64(srow0, sseg);
        const uint32_t s1 = sw64(srow1, sseg);
        *(float4*)(smem + stg + 0 * TILE_SB + s0) = pAh0;
        *(float4*)(smem + stg + 0 * TILE_SB + s1) = pAh1;
        *(float4*)(smem + stg + 1 * TILE_SB + s0) = pAl0;
        *(float4*)(smem + stg + 1 * TILE_SB + s1) = pAl1;
        *(float4*)(smem + stg + 2 * TILE_SB + s0) = pBh0;
        *(float4*)(smem + stg + 2 * TILE_SB + s1) = pBh1;
        *(float4*)(smem + stg + 3 * TILE_SB + s0) = pBl0;
        *(float4*)(smem + stg + 3 * TILE_SB + s1) = pBl1;
        __syncthreads();

        if (c + 1 < FF / KC) {
            const int kn = (c + 1) * KC;
            const size_t a0 = (size_t)(row0 + srow0) * FF + kn + sseg * 8;
            const size_t a1 = (size_t)(row0 + srow1) * FF + kn + sseg * 8;
            const size_t b0 = (size_t)(col0 + srow0) * FF + kn + sseg * 8;
            const size_t b1 = (size_t)(col0 + srow1) * FF + kn + sseg * 8;
            pAh0 = *(const float4*)(g_xhi + a0);  pAh1 = *(const float4*)(g_xhi + a1);
            pAl0 = *(const float4*)(g_xlo + a0);  pAl1 = *(const float4*)(g_xlo + a1);
            pBh0 = *(const float4*)(g_wthi + b0); pBh1 = *(const float4*)(g_wthi + b1);
            pBl0 = *(const float4*)(g_wtlo + b0); pBl1 = *(const float4*)(g_wtlo + b1);
        }

#pragma unroll
        for (int kk = 0; kk < 2; kk++) {
            const int lrow = lane & 15;
            const int lseg = 2 * kk + (lane >> 4);

            uint32_t ah[2][4], al[2][4];
#pragma unroll
            for (int i = 0; i < 2; i++) {
                int r = 32 * wm + 16 * i + lrow;
                uint32_t ad = sb + stg + 0 * TILE_SB + sw64(r, lseg);
                ldsm_x4(ah[i][0], ah[i][1], ah[i][2], ah[i][3], ad);
                ad = sb + stg + 1 * TILE_SB + sw64(r, lseg);
                ldsm_x4(al[i][0], al[i][1], al[i][2], al[i][3], ad);
            }
            uint32_t bh[8][2], bl[8][2];
#pragma unroll
            for (int jj = 0; jj < 4; jj++) {
                int r = 64 * wn + 16 * jj + lrow;
                uint32_t r0, r1, r2, r3;
                uint32_t bd = sb + stg + 2 * TILE_SB + sw64(r, lseg);
                ldsm_x4(r0, r1, r2, r3, bd);
                bh[2 * jj][0] = r0; bh[2 * jj][1] = r2;
                bh[2 * jj + 1][0] = r1; bh[2 * jj + 1][1] = r3;
                bd = sb + stg + 3 * TILE_SB + sw64(r, lseg);
                ldsm_x4(r0, r1, r2, r3, bd);
                bl[2 * jj][0] = r0; bl[2 * jj][1] = r2;
                bl[2 * jj + 1][0] = r1; bl[2 * jj + 1][1] = r3;
            }
#pragma unroll
            for (int i = 0; i < 2; i++)
#pragma unroll
                for (int j = 0; j < 8; j++) {
                    mma16816(acc[i][j], ah[i], bh[j]);
                    mma16816(acc[i][j], ah[i], bl[j]);
                    mma16816(acc[i][j], al[i], bh[j]);
                }
        }
        __syncthreads();
    }

    const int tq = lane >> 2;
    const int tr = lane & 3;
#pragma unroll
    for (int i = 0; i < 2; i++) {
        const int mbase = row0 + 32 * wm + 16 * i;
#pragma unroll
        for (int j = 0; j < 8; j++) {
            const int nbase = col0 + 64 * wn + 8 * j;
            float* p0 = &g_xg[(size_t)(mbase + tq) * G4 + nbase + 2 * tr];
            float* p1 = &g_xg[(size_t)(mbase + tq + 8) * G4 + nbase + 2 * tr];
            p0[0] = acc[i][j][0]; p0[1] = acc[i][j][1];
            p1[0] = acc[i][j][2]; p1[1] = acc[i][j][3];
        }
    }
}

// ============================================================================
// Phase 2 (warp MMA persistent): per step z = h_{t-1} @ Wh (bf16 hi/lo x3),
// Wh slice resident in SMEM; h carried as parity-buffered bf16 hi/lo.
// 128 CTAs x 256 thr; CTA owns 8 h-cols x 4 gates (N=32, M=64 batch).
// SMEM: B_hi 64K | B_lo 64K | A 2buf x (hi16K+lo16K) | zsm 64x33 fp32.
// ============================================================================
#define P2_BHI   0
#define P2_BLO   65536
#define P2_A     131072
#define P2_ABUF  32768
#define P2_Z     196608
#define P2_SMEM  (196608 + 64 * 33 * 4 + 1024)

__device__ __forceinline__ float sigmoidf_(float v) { return 1.f / (1.f + expf(-v)); }

__global__ __launch_bounds__(256, 1)
void lstm_mma_kernel(const float* __restrict__ bias, float* __restrict__ out)
{
    extern __shared__ char smem_raw[];
    char* smem = (char*)(((uintptr_t)smem_raw + 1023) & ~(uintptr_t)1023);
    const uint32_t sb = smem_u32(smem);
    float* zsm = (float*)(smem + P2_Z);     // [64][33]

    const int tid  = threadIdx.x;
    const int wid  = tid >> 5;
    const int lane = tid & 31;
    const int wm   = wid & 3;               // m16 block (batch rows wm*16..)
    const int wn   = wid >> 2;              // n16 block (gate-cols wn*16..)
    const int blk  = blockIdx.x;
    const int hc0  = blk * 8;

    // pointwise ownership: cols pc, batches pb0 / pb0+32
    const int pc  = tid & 7;
    const int pb0 = tid >> 3;               // 0..31
    float bb[4];
#pragma unroll
    for (int g = 0; g < 4; g++) bb[g] = bias[g * 1024 + hc0 + pc];
    float cell0 = 0.f, cell1 = 0.f;

    // ---- stage resident B (WhT slice, hi/lo) ----
#pragma unroll
    for (int i = 0; i < 16; i++) {
        int fi  = tid + i * 256;            // 0..4095
        int n   = fi >> 7;                  // 0..31
        int seg = fi & 127;
        int gn  = (n >> 3) * 1024 + hc0 + (n & 7);
        uint32_t so = swB2(n, seg);
        *(float4*)(smem + P2_BHI + so) = *(const float4*)(g_whthi + (size_t)gn * HH + seg * 8);
        *(float4*)(smem + P2_BLO + so) = *(const float4*)(g_whtlo + (size_t)gn * HH + seg * 8);
    }
    __syncthreads();

    // A staging decomposition: 4 float4 per matrix per thread
    int arow[4], aseg[4];
#pragma unroll
    for (int i = 0; i < 4; i++) {
        int fi = tid + i * 256;             // 0..1023
        arow[i] = fi >> 4;                  // 0..63
        aseg[i] = fi & 15;
    }

    for (int t = 0; t < TT; t++) {
        if (t > 0) {
            const __nv_bfloat16* hh = g_hhi[(t - 1) & 1];
            const __nv_bfloat16* hl = g_hlo[(t - 1) & 1];

            float acc0[4] = {0.f, 0.f, 0.f, 0.f};   // n8 block 0 of warp's n16
            float acc1[4] = {0.f, 0.f, 0.f, 0.f};   // n8 block 1

            // prefetch chunk 0
            float4 pa[4], pl[4];
#pragma unroll
            for (int i = 0; i < 4; i++) {
                size_t off = (size_t)arow[i] * HH + aseg[i] * 8;
                pa[i] = *(const float4*)(hh + off);
                pl[i] = *(const float4*)(hl + off);
            }

            for (int kc = 0; kc < HH / KH; kc++) {      // 8 chunks
                const uint32_t abase = P2_A + (uint32_t)(kc & 1) * P2_ABUF;
#pragma unroll
                for (int i = 0; i < 4; i++) {
                    uint32_t so = swA2(arow[i], aseg[i]);
                    *(float4*)(smem + abase + so)         = pa[i];
                    *(float4*)(smem + abase + 16384 + so) = pl[i];
                }
                __syncthreads();

                if (kc + 1 < HH / KH) {
                    const int kn = (kc + 1) * KH;
#pragma unroll
                    for (int i = 0; i < 4; i++) {
                        size_t off = (size_t)arow[i] * HH + kn + aseg[i] * 8;
                        pa[i] = *(const float4*)(hh + off);
                        pl[i] = *(const float4*)(hl + off);
                    }
                }

#pragma unroll
                for (int kk = 0; kk < 8; kk++) {        // k16 within chunk
                    const int lrow = lane & 15;
                    const int lseg = 2 * kk + (lane >> 4);

                    uint32_t ah[4], al[4];
                    uint32_t ad = sb + abase + swA2(wm * 16 + lrow, lseg);
                    ldsm_x4(ah[0], ah[1], ah[2], ah[3], ad);
                    ad = sb + abase + 16384 + swA2(wm * 16 + lrow, lseg);
                    ldsm_x4(al[0], al[1], al[2], al[3], ad);

                    const int nrow = wn * 16 + lrow;
                    const int bseg = kc * 16 + lseg;
                    uint32_t r0, r1, r2, r3;
                    uint32_t bd = sb + P2_BHI + swB2(nrow, bseg);
                    ldsm_x4(r0, r1, r2, r3, bd);
                    uint32_t bh0[2] = {r0, r2}, bh1[2] = {r1, r3};
                    bd = sb + P2_BLO + swB2(nrow, bseg);
                    ldsm_x4(r0, r1, r2, r3, bd);
                    uint32_t bl0[2] = {r0, r2}, bl1[2] = {r1, r3};

                    mma16816(acc0, ah, bh0);
                    mma16816(acc1, ah, bh1);
                    mma16816(acc0, ah, bl0);
                    mma16816(acc1, ah, bl1);
                    mma16816(acc0, al, bh0);
                    mma16816(acc1, al, bh1);
                }
                __syncthreads();
            }

            // dump z fragments -> zsm[64][33]
            {
                const int r  = wm * 16 + (lane >> 2);
                const int cA = wn * 16 + (lane & 3) * 2;
                zsm[r * 33 + cA]            = acc0[0];
                zsm[r * 33 + cA + 1]        = acc0[1];
                zsm[(r + 8) * 33 + cA]      = acc0[2];
                zsm[(r + 8) * 33 + cA + 1]  = acc0[3];
                zsm[r * 33 + cA + 8]        = acc1[0];
                zsm[r * 33 + cA + 9]        = acc1[1];
                zsm[(r + 8) * 33 + cA + 8]  = acc1[2];
                zsm[(r + 8) * 33 + cA + 9]  = acc1[3];
            }
            __syncthreads();
        }

        // ---- pointwise (2 batch rows per thread) ----
        const int par = t & 1;
#pragma unroll
        for (int half = 0; half < 2; half++) {
            const int b = pb0 + 32 * half;
            const float* xgp = g_xg + ((size_t)b * TT + t) * G4 + hc0 + pc;
            float zi = xgp[0]    + bb[0];
            float zf = xgp[1024] + bb[1];
            float zg = xgp[2048] + bb[2];
            float zo = xgp[3072] + bb[3];
            if (t > 0) {
                zi += zsm[b * 33 + 0 + pc];
                zf += zsm[b * 33 + 8 + pc];
                zg += zsm[b * 33 + 16 + pc];
                zo += zsm[b * 33 + 24 + pc];
            }
            float cprev = half ? cell1 : cell0;
            float cn = sigmoidf_(zf) * cprev + sigmoidf_(zi) * tanhf(zg);
            float hn = sigmoidf_(zo) * tanhf(cn);
            if (half) cell1 = cn; else cell0 = cn;

            out[((size_t)b * TT + t) * HH + hc0 + pc] = hn;
            __nv_bfloat16 hi = __float2bfloat16(hn);
            __nv_bfloat16 lo = __float2bfloat16(hn - __bfloat162float(hi));
            g_hhi[par][b * HH + hc0 + pc] = hi;
            g_hlo[par][b * HH + hc0 + pc] = lo;
        }

        // ---- grid barrier ----
        __threadfence();
        __syncthreads();
        if (tid == 0) {
            unsigned gen = g_bar_gen;
            if (atomicAdd(&g_bar_count, 1) == NCTA - 1) {
                g_bar_count = 0;
                __threadfence();
                g_bar_gen = gen + 1;
            } else {
                while (g_bar_gen == gen) { __nanosleep(64); }
            }
        }
        __syncthreads();
    }
}

// ============================================================================
// Launch: 5 graph nodes.
// ============================================================================
extern "C" void kernel_launch(void* const* d_in, const int* in_sizes, int n_in,
                              void* d_out, int out_size)
{
    const float* x  = (const float*)d_in[0];   // [64, 512, 1024]
    const float* Wx = (const float*)d_in[1];   // [1024, 4096]
    const float* Wh = (const float*)d_in[2];   // [1024, 4096]
    const float* b  = (const float*)d_in[3];   // [4096]
    float* out = (float*)d_out;                // [64, 512, 1024]

    cudaFuncSetAttribute(gemm_mma_kernel,
                         cudaFuncAttributeMaxDynamicSharedMemorySize, SMEM_DYN);
    cudaFuncSetAttribute(lstm_mma_kernel,
                         cudaFuncAttributeMaxDynamicSharedMemorySize, P2_SMEM);

    // converts (destination selected device-side: 0 -> Wx buffers, 1 -> Wh)
    convert_x_kernel<<<(int)(((size_t)MROWS * FF / 4) / 256), 256>>>(x);
    convert_wt_kernel<<<(int)(((size_t)FF * G4) / 256), 256>>>(Wx, 0);
    convert_wt_kernel<<<(int)(((size_t)FF * G4) / 256), 256>>>(Wh, 1);

    // Phase 1: warp-MMA GEMM
    {
        dim3 grid(G4 / 128, MROWS / 128);   // (32, 256)
        gemm_mma_kernel<<<grid, 256, SMEM_DYN>>>();
    }

    // Phase 2: persistent warp-MMA recurrence
    lstm_mma_kernel<<<NCTA, 256, P2_SMEM>>>(b, out);
}

// round 11
// speedup vs baseline: 1.9595x; 1.1997x over previous
#include <cuda_runtime.h>
#include <cuda_bf16.h>
#include <math.h>
#include <cstdint>

// Problem constants
#define BATCH 64
#define TT    512
#define FF    1024
#define HH    1024
#define G4    4096
#define NCTA  256           // phase-2 CTAs (2 per SM on 148 SMs -> co-resident)
#define MROWS (BATCH * TT)

// ---------------- scratch (static device memory; no allocations) ------------
static __device__ float          g_xg[(size_t)MROWS * G4];
static __device__ __nv_bfloat16  g_xhi[(size_t)MROWS * FF];
static __device__ __nv_bfloat16  g_xlo[(size_t)MROWS * FF];
static __device__ __nv_bfloat16  g_wthi[(size_t)G4 * FF];     // WxT [n][k]
static __device__ __nv_bfloat16  g_wtlo[(size_t)G4 * FF];
static __device__ __nv_bfloat16  g_whthi[(size_t)G4 * HH];    // WhT [n][k]
static __device__ __nv_bfloat16  g_whtlo[(size_t)G4 * HH];
static __device__ __nv_bfloat16  g_hhi[2][BATCH * HH];
static __device__ __nv_bfloat16  g_hlo[2][BATCH * HH];
static __device__ unsigned       g_bar_count;
static __device__ volatile unsigned g_bar_gen;

// ======================= baseline-PTX MMA helpers ===========================
__device__ __forceinline__ uint32_t smem_u32(const void* p) {
    uint32_t a;
    asm("{ .reg .u64 t; cvta.to.shared.u64 t, %1; cvt.u32.u64 %0, t; }"
        : "=r"(a) : "l"(p));
    return a;
}
__device__ __forceinline__ void ldsm_x4(uint32_t& r0, uint32_t& r1,
                                        uint32_t& r2, uint32_t& r3, uint32_t addr) {
    asm volatile("ldmatrix.sync.aligned.m8n8.x4.shared.b16 {%0,%1,%2,%3}, [%4];"
                 : "=r"(r0), "=r"(r1), "=r"(r2), "=r"(r3) : "r"(addr));
}
__device__ __forceinline__ void ldsm_x2(uint32_t& r0, uint32_t& r1, uint32_t addr) {
    asm volatile("ldmatrix.sync.aligned.m8n8.x2.shared.b16 {%0,%1}, [%2];"
                 : "=r"(r0), "=r"(r1) : "r"(addr));
}
__device__ __forceinline__ void mma16816(float* d, const uint32_t* a, const uint32_t* b) {
    asm volatile(
        "mma.sync.aligned.m16n8k16.row.col.f32.bf16.bf16.f32 "
        "{%0,%1,%2,%3}, {%4,%5,%6,%7}, {%8,%9}, {%0,%1,%2,%3};"
        : "+f"(d[0]), "+f"(d[1]), "+f"(d[2]), "+f"(d[3])
        : "r"(a[0]), "r"(a[1]), "r"(a[2]), "r"(a[3]), "r"(b[0]), "r"(b[1]));
}
// 64B-row swizzle (phase-1 tiles)
__device__ __forceinline__ uint32_t sw64(int row, int seg) {
    return (uint32_t)(row * 64 + ((seg ^ ((row >> 1) & 3)) << 4));
}
// phase-2: A rows 128B (8 segs), B rows 2048B (128 segs)
__device__ __forceinline__ uint32_t swA2(int row, int seg) {
    return (uint32_t)((row << 7) + ((seg ^ (row & 7)) << 4));
}
__device__ __forceinline__ uint32_t swB2(int n, int seg) {
    return (uint32_t)((n << 11) + ((seg ^ (n & 7)) << 4));
}

// ============================================================================
// Conversions
// ============================================================================
__global__ __launch_bounds__(256)
void convert_x_kernel(const float* __restrict__ x)
{
    size_t i = (size_t)blockIdx.x * blockDim.x + threadIdx.x;
    float4 v = ((const float4*)x)[i];
    float vv[4] = {v.x, v.y, v.z, v.w};
    __nv_bfloat16 hi[4], lo[4];
#pragma unroll
    for (int j = 0; j < 4; j++) {
        hi[j] = __float2bfloat16(vv[j]);
        lo[j] = __float2bfloat16(vv[j] - __bfloat162float(hi[j]));
    }
    __nv_bfloat162* xh = (__nv_bfloat162*)g_xhi;
    __nv_bfloat162* xl = (__nv_bfloat162*)g_xlo;
    xh[2 * i]     = __halves2bfloat162(hi[0], hi[1]);
    xh[2 * i + 1] = __halves2bfloat162(hi[2], hi[3]);
    xl[2 * i]     = __halves2bfloat162(lo[0], lo[1]);
    xl[2 * i + 1] = __halves2bfloat162(lo[2], lo[3]);
}

__global__ __launch_bounds__(256)
void convert_wt_kernel(const float* __restrict__ src, int which)
{
    __nv_bfloat16* dhi = which ? g_whthi : g_wthi;
    __nv_bfloat16* dlo = which ? g_whtlo : g_wtlo;
    size_t idx = (size_t)blockIdx.x * blockDim.x + threadIdx.x;
    int k = (int)(idx >> 12);
    int n = (int)(idx & 4095);
    float v = src[idx];
    __nv_bfloat16 hi = __float2bfloat16(v);
    __nv_bfloat16 lo = __float2bfloat16(v - __bfloat162float(hi));
    dhi[(size_t)n * FF + k] = hi;
    dlo[(size_t)n * FF + k] = lo;
}

// ============================================================================
// Phase 1: xg = x @ Wx, bf16 hi/lo x3. CTA tile 128x64, warp m32n32,
// 2 CTAs/SM. SMEM/buf: Ahi 8K | Alo 8K | Bhi 4K | Blo 4K.
// ============================================================================
#define P1_AHI 0
#define P1_ALO 8192
#define P1_BHI 16384
#define P1_BLO 20480
#define P1_BUF 24576
#define SMEM_DYN (2 * P1_BUF + 1024)

__global__ __launch_bounds__(256, 2)
void gemm_mma_kernel()
{
    extern __shared__ char smem_raw[];
    char* smem = (char*)(((uintptr_t)smem_raw + 1023) & ~(uintptr_t)1023);
    const uint32_t sb = smem_u32(smem);

    const int tid = threadIdx.x;
    const int wid = tid >> 5;
    const int lane = tid & 31;
    const int wm = wid & 3;            // m32 block
    const int wn = wid >> 2;           // n32 block (0..1)
    const int col0 = blockIdx.x * 64;  // N block (fast)
    const int row0 = blockIdx.y * 128;

    // staging: A 2 float4/thread per matrix, B 1
    const int ar0 = tid >> 2;          // 0..63 (A rows ar0, ar0+64)
    const int asg = tid & 3;
    const int br0 = tid >> 2;          // 0..63
    const int bsg = tid & 3;

    float acc[2][4][4];
#pragma unroll
    for (int i = 0; i < 2; i++)
#pragma unroll
        for (int j = 0; j < 4; j++)
#pragma unroll
            for (int q = 0; q < 4; q++) acc[i][j][q] = 0.f;

    float4 pAh[2], pAl[2], pBh, pBl;
#pragma unroll
    for (int i = 0; i < 2; i++) {
        const size_t a = (size_t)(row0 + ar0 + 64 * i) * FF + asg * 8;
        pAh[i] = *(const float4*)(g_xhi + a);
        pAl[i] = *(const float4*)(g_xlo + a);
    }
    {
        const size_t b = (size_t)(col0 + br0) * FF + bsg * 8;
        pBh = *(const float4*)(g_wthi + b);
        pBl = *(const float4*)(g_wtlo + b);
    }

    for (int c = 0; c < 32; c++) {               // K chunks of 32
        const uint32_t stg = (uint32_t)(c & 1) * P1_BUF;
#pragma unroll
        for (int i = 0; i < 2; i++) {
            const uint32_t so = sw64(ar0 + 64 * i, asg);
            *(float4*)(smem + stg + P1_AHI + so) = pAh[i];
            *(float4*)(smem + stg + P1_ALO + so) = pAl[i];
        }
        {
            const uint32_t so = sw64(br0, bsg);
            *(float4*)(smem + stg + P1_BHI + so) = pBh;
            *(float4*)(smem + stg + P1_BLO + so) = pBl;
        }
        __syncthreads();

        if (c + 1 < 32) {
            const int kn = (c + 1) * 32;
#pragma unroll
            for (int i = 0; i < 2; i++) {
                const size_t a = (size_t)(row0 + ar0 + 64 * i) * FF + kn + asg * 8;
                pAh[i] = *(const float4*)(g_xhi + a);
                pAl[i] = *(const float4*)(g_xlo + a);
            }
            const size_t b = (size_t)(col0 + br0) * FF + kn + bsg * 8;
            pBh = *(const float4*)(g_wthi + b);
            pBl = *(const float4*)(g_wtlo + b);
        }

#pragma unroll
        for (int kk = 0; kk < 2; kk++) {
            const int lrow = lane & 15;
            const int lseg = 2 * kk + (lane >> 4);

            uint32_t ah[2][4], al[2][4];
#pragma unroll
            for (int i = 0; i < 2; i++) {
                const int r = 32 * wm + 16 * i + lrow;
                ldsm_x4(ah[i][0], ah[i][1], ah[i][2], ah[i][3],
                        sb + stg + P1_AHI + sw64(r, lseg));
                ldsm_x4(al[i][0], al[i][1], al[i][2], al[i][3],
                        sb + stg + P1_ALO + sw64(r, lseg));
            }
            uint32_t bh[4][2], bl[4][2];
#pragma unroll
            for (int jj = 0; jj < 2; jj++) {
                const int r = 32 * wn + 16 * jj + lrow;
                uint32_t r0, r1, r2, r3;
                ldsm_x4(r0, r1, r2, r3, sb + stg + P1_BHI + sw64(r, lseg));
                bh[2 * jj][0] = r0; bh[2 * jj][1] = r2;
                bh[2 * jj + 1][0] = r1; bh[2 * jj + 1][1] = r3;
                ldsm_x4(r0, r1, r2, r3, sb + stg + P1_BLO + sw64(r, lseg));
                bl[2 * jj][0] = r0; bl[2 * jj][1] = r2;
                bl[2 * jj + 1][0] = r1; bl[2 * jj + 1][1] = r3;
            }
#pragma unroll
            for (int i = 0; i < 2; i++)
#pragma unroll
                for (int j = 0; j < 4; j++) {
                    mma16816(acc[i][j], ah[i], bh[j]);
                    mma16816(acc[i][j], ah[i], bl[j]);
                    mma16816(acc[i][j], al[i], bh[j]);
                }
        }
        __syncthreads();
    }

    const int tq = lane >> 2;
    const int tr = lane & 3;
#pragma unroll
    for (int i = 0; i < 2; i++) {
        const int mbase = row0 + 32 * wm + 16 * i;
#pragma unroll
        for (int j = 0; j < 4; j++) {
            const int nbase = col0 + 32 * wn + 8 * j;
            float* p0 = &g_xg[(size_t)(mbase + tq) * G4 + nbase + 2 * tr];
            float* p1 = &g_xg[(size_t)(mbase + tq + 8) * G4 + nbase + 2 * tr];
            p0[0] = acc[i][j][0]; p0[1] = acc[i][j][1];
            p1[0] = acc[i][j][2]; p1[1] = acc[i][j][3];
        }
    }
}

// ============================================================================
// Phase 2: persistent warp-MMA recurrence, 256 CTAs (2/SM), N=16 per CTA.
// SMEM: Bhi 32K | Blo 32K | A 2buf x (hi8K+lo8K) | zsm 64x17 fp32.
// ============================================================================
#define P2_BHI   0
#define P2_BLO   32768
#define P2_A     65536
#define P2_ABUF  16384
#define P2_Z     98304
#define P2_SMEM  (98304 + 64 * 17 * 4 + 1024)
#define KH2      64

__device__ __forceinline__ float sigmoidf_(float v) { return 1.f / (1.f + expf(-v)); }

__global__ __launch_bounds__(256, 2)
void lstm_mma_kernel(const float* __restrict__ bias, float* __restrict__ out)
{
    extern __shared__ char smem_raw[];
    char* smem = (char*)(((uintptr_t)smem_raw + 1023) & ~(uintptr_t)1023);
    const uint32_t sb = smem_u32(smem);
    float* zsm = (float*)(smem + P2_Z);       // [64][17]

    const int tid  = threadIdx.x;
    const int wid  = tid >> 5;
    const int lane = tid & 31;
    const int wm   = wid & 3;                 // m16 (batch rows wm*16..)
    const int wn   = wid >> 2;                // n8 block (0..1)
    const int blk  = blockIdx.x;              // 0..255
    const int hc0  = blk * 4;                 // 4 h-cols per CTA

    // pointwise: 1 (batch, h-col) per thread
    const int pb  = tid >> 2;                 // 0..63
    const int phl = tid & 3;                  // 0..3
    float bb[4];
#pragma unroll
    for (int g = 0; g < 4; g++) bb[g] = bias[g * 1024 + hc0 + phl];
    float cell = 0.f;

    // resident B (WhT slice): 16 n x 1024 k, hi/lo
#pragma unroll
    for (int i = 0; i < 8; i++) {
        int fi  = tid + i * 256;              // 0..2047
        int n   = fi >> 7;                    // 0..15
        int seg = fi & 127;
        int gn  = (n >> 2) * 1024 + hc0 + (n & 3);
        uint32_t so = swB2(n, seg);
        *(float4*)(smem + P2_BHI + so) = *(const float4*)(g_whthi + (size_t)gn * HH + seg * 8);
        *(float4*)(smem + P2_BLO + so) = *(const float4*)(g_whtlo + (size_t)gn * HH + seg * 8);
    }
    __syncthreads();

    // A staging: 2 float4/thread per matrix; rows ar, ar+32, seg asg
    const int ar  = tid >> 3;                 // 0..31
    const int asg = tid & 7;

    for (int t = 0; t < TT; t++) {
        // prefetch this step's xg early (DRAM latency hidden behind GEMM)
        float xv[4];
#pragma unroll
        for (int g = 0; g < 4; g++)
            xv[g] = g_xg[((size_t)pb * TT + t) * G4 + g * 1024 + hc0 + phl];

        if (t > 0) {
            const __nv_bfloat16* hh = g_hhi[(t - 1) & 1];
            const __nv_bfloat16* hl = g_hlo[(t - 1) & 1];

            float acc[4] = {0.f, 0.f, 0.f, 0.f};

            float4 pa[2], pl[2];
#pragma unroll
            for (int i = 0; i < 2; i++) {
                const size_t off = (size_t)(ar + 32 * i) * HH + asg * 8;
                pa[i] = *(const float4*)(hh + off);
                pl[i] = *(const float4*)(hl + off);
            }

            for (int kc = 0; kc < HH / KH2; kc++) {   // 16 chunks of 64
                const uint32_t abase = P2_A + (uint32_t)(kc & 1) * P2_ABUF;
#pragma unroll
                for (int i = 0; i < 2; i++) {
                    const uint32_t so = swA2(ar + 32 * i, asg);
                    *(float4*)(smem + abase + so)        = pa[i];
                    *(float4*)(smem + abase + 8192 + so) = pl[i];
                }
                __syncthreads();

                if (kc + 1 < HH / KH2) {
                    const int kn = (kc + 1) * KH2;
#pragma unroll
                    for (int i = 0; i < 2; i++) {
                        const size_t off = (size_t)(ar + 32 * i) * HH + kn + asg * 8;
                        pa[i] = *(const float4*)(hh + off);
                        pl[i] = *(const float4*)(hl + off);
                    }
                }

#pragma unroll
                for (int kk = 0; kk < 4; kk++) {
                    const int lrow = lane & 15;
                    const int lsegA = 2 * kk + (lane >> 4);   // 0..7

                    uint32_t ah[4], al[4];
                    ldsm_x4(ah[0], ah[1], ah[2], ah[3],
                            sb + abase + swA2(wm * 16 + lrow, lsegA));
                    ldsm_x4(al[0], al[1], al[2], al[3],
                            sb + abase + 8192 + swA2(wm * 16 + lrow, lsegA));

                    const int l = lane & 15;
                    const int brow = wn * 8 + (l & 7);
                    const int bseg = 2 * (kc * 4 + kk) + (l >> 3);  // 0..127
                    uint32_t bh[2], bl[2];
                    ldsm_x2(bh[0], bh[1], sb + P2_BHI + swB2(brow, bseg));
                    ldsm_x2(bl[0], bl[1], sb + P2_BLO + swB2(brow, bseg));

                    mma16816(acc, ah, bh);
                    mma16816(acc, ah, bl);
                    mma16816(acc, al, bh);
                }
                __syncthreads();
            }

            // dump z fragment -> zsm[64][17]
            {
                const int r = wm * 16 + (lane >> 2);
                const int c = wn * 8 + (lane & 3) * 2;
                zsm[r * 17 + c]           = acc[0];
                zsm[r * 17 + c + 1]       = acc[1];
                zsm[(r + 8) * 17 + c]     = acc[2];
                zsm[(r + 8) * 17 + c + 1] = acc[3];
            }
            __syncthreads();
        }

        // ---- pointwise ----
        {
            float zi = xv[0] + bb[0];
            float zf = xv[1] + bb[1];
            float zg = xv[2] + bb[2];
            float zo = xv[3] + bb[3];
            if (t > 0) {
                zi += zsm[pb * 17 + 0  + phl];
                zf += zsm[pb * 17 + 4  + phl];
                zg += zsm[pb * 17 + 8  + phl];
                zo += zsm[pb * 17 + 12 + phl];
            }
            float cn = sigmoidf_(zf) * cell + sigmoidf_(zi) * tanhf(zg);
            float hn = sigmoidf_(zo) * tanhf(cn);
            cell = cn;

            out[((size_t)pb * TT + t) * HH + hc0 + phl] = hn;
            __nv_bfloat16 hi = __float2bfloat16(hn);
            __nv_bfloat16 lo = __float2bfloat16(hn - __bfloat162float(hi));
            g_hhi[t & 1][pb * HH + hc0 + phl] = hi;
            g_hlo[t & 1][pb * HH + hc0 + phl] = lo;
        }

        // ---- grid barrier ----
        __threadfence();
        __syncthreads();
        if (tid == 0) {
            unsigned gen = g_bar_gen;
            if (atomicAdd(&g_bar_count, 1) == NCTA - 1) {
                g_bar_count = 0;
                __threadfence();
                g_bar_gen = gen + 1;
            } else {
                while (g_bar_gen == gen) { __nanosleep(64); }
            }
        }
        __syncthreads();
    }
}

// ============================================================================
// Launch: 5 graph nodes.
// ============================================================================
extern "C" void kernel_launch(void* const* d_in, const int* in_sizes, int n_in,
                              void* d_out, int out_size)
{
    const float* x  = (const float*)d_in[0];
    const float* Wx = (const float*)d_in[1];
    const float* Wh = (const float*)d_in[2];
    const float* b  = (const float*)d_in[3];
    float* out = (float*)d_out;

    cudaFuncSetAttribute(gemm_mma_kernel,
                         cudaFuncAttributeMaxDynamicSharedMemorySize, SMEM_DYN);
    cudaFuncSetAttribute(lstm_mma_kernel,
                         cudaFuncAttributeMaxDynamicSharedMemorySize, P2_SMEM);

    convert_x_kernel<<<(int)(((size_t)MROWS * FF / 4) / 256), 256>>>(x);
    convert_wt_kernel<<<(int)(((size_t)FF * G4) / 256), 256>>>(Wx, 0);
    convert_wt_kernel<<<(int)(((size_t)FF * G4) / 256), 256>>>(Wh, 1);

    {
        dim3 grid(G4 / 64, MROWS / 128);   // (64, 256) = 16384 CTAs
        gemm_mma_kernel<<<grid, 256, SMEM_DYN>>>();
    }

    lstm_mma_kernel<<<NCTA, 256, P2_SMEM>>>(b, out);
}

// round 12
// speedup vs baseline: 2.5784x; 1.3158x over previous
#include <cuda_runtime.h>
#include <cuda_bf16.h>
#include <math.h>
#include <cstdint>

// Problem constants
#define BATCH 64
#define TT    512
#define FF    1024
#define HH    1024
#define G4    4096
#define NCTA  256           // phase-2: 64 N-groups x 4 K-splits, 2/SM co-resident
#define MROWS (BATCH * TT)

// ---------------- scratch (static device memory; no allocations) ------------
static __device__ float          g_xg[(size_t)MROWS * G4];
static __device__ __nv_bfloat16  g_xhi[(size_t)MROWS * FF];
static __device__ __nv_bfloat16  g_xlo[(size_t)MROWS * FF];
static __device__ __nv_bfloat16  g_wthi[(size_t)G4 * FF];     // WxT [n][k]
static __device__ __nv_bfloat16  g_wtlo[(size_t)G4 * FF];
static __device__ __nv_bfloat16  g_whthi[(size_t)G4 * HH];    // WhT [n][k]
static __device__ __nv_bfloat16  g_whtlo[(size_t)G4 * HH];
static __device__ __nv_bfloat16  g_hhi[2][BATCH * HH];
static __device__ __nv_bfloat16  g_hlo[2][BATCH * HH];
static __device__ float          g_zpart[NCTA * BATCH * 64];  // [g*4+ks][b][64]
static __device__ unsigned       g_flags[64];                 // per-group arrivals
static __device__ unsigned       g_bar_count;
static __device__ volatile unsigned g_bar_gen;

// ======================= baseline-PTX MMA helpers ===========================
__device__ __forceinline__ uint32_t smem_u32(const void* p) {
    uint32_t a;
    asm("{ .reg .u64 t; cvta.to.shared.u64 t, %1; cvt.u32.u64 %0, t; }"
        : "=r"(a) : "l"(p));
    return a;
}
__device__ __forceinline__ void ldsm_x4(uint32_t& r0, uint32_t& r1,
                                        uint32_t& r2, uint32_t& r3, uint32_t addr) {
    asm volatile("ldmatrix.sync.aligned.m8n8.x4.shared.b16 {%0,%1,%2,%3}, [%4];"
                 : "=r"(r0), "=r"(r1), "=r"(r2), "=r"(r3) : "r"(addr));
}
__device__ __forceinline__ void mma16816(float* d, const uint32_t* a, const uint32_t* b) {
    asm volatile(
        "mma.sync.aligned.m16n8k16.row.col.f32.bf16.bf16.f32 "
        "{%0,%1,%2,%3}, {%4,%5,%6,%7}, {%8,%9}, {%0,%1,%2,%3};"
        : "+f"(d[0]), "+f"(d[1]), "+f"(d[2]), "+f"(d[3])
        : "r"(a[0]), "r"(a[1]), "r"(a[2]), "r"(a[3]), "r"(b[0]), "r"(b[1]));
}
// phase-1: 64B rows
__device__ __forceinline__ uint32_t sw64(int row, int seg) {
    return (uint32_t)(row * 64 + ((seg ^ ((row >> 1) & 3)) << 4));
}
// phase-2: A rows 128B (8 segs), B rows 512B (32 segs)
__device__ __forceinline__ uint32_t swA3(int row, int seg) {
    return (uint32_t)((row << 7) + ((seg ^ (row & 7)) << 4));
}
__device__ __forceinline__ uint32_t swB3(int n, int seg) {
    return (uint32_t)((n << 9) + ((seg ^ (n & 7)) << 4));
}

// ============================================================================
// Conversions
// ============================================================================
__global__ __launch_bounds__(256)
void convert_x_kernel(const float* __restrict__ x)
{
    size_t i = (size_t)blockIdx.x * blockDim.x + threadIdx.x;
    float4 v = ((const float4*)x)[i];
    float vv[4] = {v.x, v.y, v.z, v.w};
    __nv_bfloat16 hi[4], lo[4];
#pragma unroll
    for (int j = 0; j < 4; j++) {
        hi[j] = __float2bfloat16(vv[j]);
        lo[j] = __float2bfloat16(vv[j] - __bfloat162float(hi[j]));
    }
    __nv_bfloat162* xh = (__nv_bfloat162*)g_xhi;
    __nv_bfloat162* xl = (__nv_bfloat162*)g_xlo;
    xh[2 * i]     = __halves2bfloat162(hi[0], hi[1]);
    xh[2 * i + 1] = __halves2bfloat162(hi[2], hi[3]);
    xl[2 * i]     = __halves2bfloat162(lo[0], lo[1]);
    xl[2 * i + 1] = __halves2bfloat162(lo[2], lo[3]);
}

__global__ __launch_bounds__(256)
void convert_wt_kernel(const float* __restrict__ src, int which)
{
    __nv_bfloat16* dhi = which ? g_whthi : g_wthi;
    __nv_bfloat16* dlo = which ? g_whtlo : g_wtlo;
    size_t idx = (size_t)blockIdx.x * blockDim.x + threadIdx.x;
    int k = (int)(idx >> 12);
    int n = (int)(idx & 4095);
    float v = src[idx];
    __nv_bfloat16 hi = __float2bfloat16(v);
    __nv_bfloat16 lo = __float2bfloat16(v - __bfloat162float(hi));
    dhi[(size_t)n * FF + k] = hi;
    dlo[(size_t)n * FF + k] = lo;
}

// ============================================================================
// Phase 1: xg = x @ Wx, bf16 hi/lo x3. CTA 128x64, warp m32n32, 2 CTAs/SM.
// (validated R11)
// ============================================================================
#define P1_AHI 0
#define P1_ALO 8192
#define P1_BHI 16384
#define P1_BLO 20480
#define P1_BUF 24576
#define SMEM_DYN (2 * P1_BUF + 1024)

__global__ __launch_bounds__(256, 2)
void gemm_mma_kernel()
{
    extern __shared__ char smem_raw[];
    char* smem = (char*)(((uintptr_t)smem_raw + 1023) & ~(uintptr_t)1023);
    const uint32_t sb = smem_u32(smem);

    const int tid = threadIdx.x;
    const int wid = tid >> 5;
    const int lane = tid & 31;
    const int wm = wid & 3;
    const int wn = wid >> 2;
    const int col0 = blockIdx.x * 64;
    const int row0 = blockIdx.y * 128;

    const int ar0 = tid >> 2;
    const int asg = tid & 3;
    const int br0 = tid >> 2;
    const int bsg = tid & 3;

    float acc[2][4][4];
#pragma unroll
    for (int i = 0; i < 2; i++)
#pragma unroll
        for (int j = 0; j < 4; j++)
#pragma unroll
            for (int q = 0; q < 4; q++) acc[i][j][q] = 0.f;

    float4 pAh[2], pAl[2], pBh, pBl;
#pragma unroll
    for (int i = 0; i < 2; i++) {
        const size_t a = (size_t)(row0 + ar0 + 64 * i) * FF + asg * 8;
        pAh[i] = *(const float4*)(g_xhi + a);
        pAl[i] = *(const float4*)(g_xlo + a);
    }
    {
        const size_t b = (size_t)(col0 + br0) * FF + bsg * 8;
        pBh = *(const float4*)(g_wthi + b);
        pBl = *(const float4*)(g_wtlo + b);
    }

    for (int c = 0; c < 32; c++) {
        const uint32_t stg = (uint32_t)(c & 1) * P1_BUF;
#pragma unroll
        for (int i = 0; i < 2; i++) {
            const uint32_t so = sw64(ar0 + 64 * i, asg);
            *(float4*)(smem + stg + P1_AHI + so) = pAh[i];
            *(float4*)(smem + stg + P1_ALO + so) = pAl[i];
        }
        {
            const uint32_t so = sw64(br0, bsg);
            *(float4*)(smem + stg + P1_BHI + so) = pBh;
            *(float4*)(smem + stg + P1_BLO + so) = pBl;
        }
        __syncthreads();

        if (c + 1 < 32) {
            const int kn = (c + 1) * 32;
#pragma unroll
            for (int i = 0; i < 2; i++) {
                const size_t a = (size_t)(row0 + ar0 + 64 * i) * FF + kn + asg * 8;
                pAh[i] = *(const float4*)(g_xhi + a);
                pAl[i] = *(const float4*)(g_xlo + a);
            }
            const size_t b = (size_t)(col0 + br0) * FF + kn + bsg * 8;
            pBh = *(const float4*)(g_wthi + b);
            pBl = *(const float4*)(g_wtlo + b);
        }

#pragma unroll
        for (int kk = 0; kk < 2; kk++) {
            const int lrow = lane & 15;
            const int lseg = 2 * kk + (lane >> 4);

            uint32_t ah[2][4], al[2][4];
#pragma unroll
            for (int i = 0; i < 2; i++) {
                const int r = 32 * wm + 16 * i + lrow;
                ldsm_x4(ah[i][0], ah[i][1], ah[i][2], ah[i][3],
                        sb + stg + P1_AHI + sw64(r, lseg));
                ldsm_x4(al[i][0], al[i][1], al[i][2], al[i][3],
                        sb + stg + P1_ALO + sw64(r, lseg));
            }
            uint32_t bh[4][2], bl[4][2];
#pragma unroll
            for (int jj = 0; jj < 2; jj++) {
                const int r = 32 * wn + 16 * jj + lrow;
                uint32_t r0, r1, r2, r3;
                ldsm_x4(r0, r1, r2, r3, sb + stg + P1_BHI + sw64(r, lseg));
                bh[2 * jj][0] = r0; bh[2 * jj][1] = r2;
                bh[2 * jj + 1][0] = r1; bh[2 * jj + 1][1] = r3;
                ldsm_x4(r0, r1, r2, r3, sb + stg + P1_BLO + sw64(r, lseg));
                bl[2 * jj][0] = r0; bl[2 * jj][1] = r2;
                bl[2 * jj + 1][0] = r1; bl[2 * jj + 1][1] = r3;
            }
#pragma unroll
            for (int i = 0; i < 2; i++)
#pragma unroll
                for (int j = 0; j < 4; j++) {
                    mma16816(acc[i][j], ah[i], bh[j]);
                    mma16816(acc[i][j], ah[i], bl[j]);
                    mma16816(acc[i][j], al[i], bh[j]);
                }
        }
        __syncthreads();
    }

    const int tq = lane >> 2;
    const int tr = lane & 3;
#pragma unroll
    for (int i = 0; i < 2; i++) {
        const int mbase = row0 + 32 * wm + 16 * i;
#pragma unroll
        for (int j = 0; j < 4; j++) {
            const int nbase = col0 + 32 * wn + 8 * j;
            float* p0 = &g_xg[(size_t)(mbase + tq) * G4 + nbase + 2 * tr];
            float* p1 = &g_xg[(size_t)(mbase + tq + 8) * G4 + nbase + 2 * tr];
            p0[0] = acc[i][j][0]; p0[1] = acc[i][j][1];
            p1[0] = acc[i][j][2]; p1[1] = acc[i][j][3];
        }
    }
}

// ============================================================================
// Phase 2: persistent K-split recurrence.
// CTA (g, ks): z_part[g,ks] = h[:, ks*256:+256] @ WhT-slice(64 gate-cols).
// B resident 64KB; A 64x64k chunks double-buffered; partials -> global;
// per-group flag sync; pointwise split by batch quarter; 1 parity barrier.
// ============================================================================
#define P2_BHI   0
#define P2_BLO   32768
#define P2_A     65536
#define P2_ABUF  16384
#define P2_SMEM  (65536 + 32768 + 1024)

__device__ __forceinline__ float sigmoidf_(float v) { return 1.f / (1.f + expf(-v)); }

__global__ __launch_bounds__(256, 2)
void lstm_mma_kernel(const float* __restrict__ bias, float* __restrict__ out)
{
    extern __shared__ char smem_raw[];
    char* smem = (char*)(((uintptr_t)smem_raw + 1023) & ~(uintptr_t)1023);
    const uint32_t sb = smem_u32(smem);

    const int tid  = threadIdx.x;
    const int wid  = tid >> 5;
    const int lane = tid & 31;
    const int wm   = wid & 3;               // m16 (batch rows)
    const int wn   = wid >> 2;              // n32 block (0..1)
    const int g    = blockIdx.x >> 2;       // N-group 0..63
    const int ks   = blockIdx.x & 3;        // K-split 0..3
    const int kbase = ks * 256;

    __shared__ unsigned s_base;

    // pointwise ownership: batch b = ks*16 + (tid>>4), h-col hl = tid&15
    const int pb = ks * 16 + (tid >> 4);
    const int hl = tid & 15;
    const int hcol = g * 16 + hl;
    float bb[4];
#pragma unroll
    for (int gt = 0; gt < 4; gt++) bb[gt] = bias[gt * 1024 + hcol];
    float cell = 0.f;

    // ---- resident B: 64 n x 256 k slice, hi/lo ----
#pragma unroll
    for (int i = 0; i < 8; i++) {
        int fi  = tid + i * 256;            // 0..2047
        int n   = fi >> 5;                  // 0..63
        int seg = fi & 31;
        int gn  = (n >> 4) * 1024 + g * 16 + (n & 15);
        uint32_t so = swB3(n, seg);
        const size_t src = (size_t)gn * HH + kbase + seg * 8;
        *(float4*)(smem + P2_BHI + so) = *(const float4*)(g_whthi + src);
        *(float4*)(smem + P2_BLO + so) = *(const float4*)(g_whtlo + src);
    }
    __syncthreads();

    // A staging: rows ar, ar+32; seg asg (2 float4/thread/matrix)
    const int ar  = tid >> 3;               // 0..31
    const int asg = tid & 7;

    float* zpart_self = g_zpart + (size_t)(g * 4 + ks) * BATCH * 64;

    for (int t = 0; t < TT; t++) {
        if (t == 0 && tid == 0) s_base = g_flags[g];

        // prefetch this step's xg for pointwise
        float xv[4];
#pragma unroll
        for (int gt = 0; gt < 4; gt++)
            xv[gt] = g_xg[((size_t)pb * TT + t) * G4 + gt * 1024 + hcol];

        if (t > 0) {
            const __nv_bfloat16* hh = g_hhi[(t - 1) & 1];
            const __nv_bfloat16* hl_ = g_hlo[(t - 1) & 1];

            float acc[4][4];
#pragma unroll
            for (int j = 0; j < 4; j++)
#pragma unroll
                for (int q = 0; q < 4; q++) acc[j][q] = 0.f;

            float4 pa[2], pl[2];
#pragma unroll
            for (int i = 0; i < 2; i++) {
                const size_t off = (size_t)(ar + 32 * i) * HH + kbase + asg * 8;
                pa[i] = *(const float4*)(hh + off);
                pl[i] = *(const float4*)(hl_ + off);
            }

            for (int kc = 0; kc < 4; kc++) {        // 4 chunks of 64k
                const uint32_t abase = P2_A + (uint32_t)(kc & 1) * P2_ABUF;
#pragma unroll
                for (int i = 0; i < 2; i++) {
                    const uint32_t so = swA3(ar + 32 * i, asg);
                    *(float4*)(smem + abase + so)        = pa[i];
                    *(float4*)(smem + abase + 8192 + so) = pl[i];
                }
                __syncthreads();

                if (kc + 1 < 4) {
                    const int kn = kbase + (kc + 1) * 64;
#pragma unroll
                    for (int i = 0; i < 2; i++) {
                        const size_t off = (size_t)(ar + 32 * i) * HH + kn + asg * 8;
                        pa[i] = *(const float4*)(hh + off);
                        pl[i] = *(const float4*)(hl_ + off);
                    }
                }

#pragma unroll
                for (int kk = 0; kk < 4; kk++) {
                    const int lrow = lane & 15;
                    const int hs   = lane >> 4;
                    const int aseg2 = 2 * kk + hs;          // 0..7
                    const int bseg2 = 2 * (kc * 4 + kk) + hs; // 0..31

                    uint32_t ah[4], al[4];
                    ldsm_x4(ah[0], ah[1], ah[2], ah[3],
                            sb + abase + swA3(wm * 16 + lrow, aseg2));
                    ldsm_x4(al[0], al[1], al[2], al[3],
                            sb + abase + 8192 + swA3(wm * 16 + lrow, aseg2));

                    uint32_t bh[4][2], bl[4][2];
#pragma unroll
                    for (int jj = 0; jj < 2; jj++) {
                        const int r = wn * 32 + 16 * jj + lrow;
                        uint32_t r0, r1, r2, r3;
                        ldsm_x4(r0, r1, r2, r3, sb + P2_BHI + swB3(r, bseg2));
                        bh[2 * jj][0] = r0; bh[2 * jj][1] = r2;
                        bh[2 * jj + 1][0] = r1; bh[2 * jj + 1][1] = r3;
                        ldsm_x4(r0, r1, r2, r3, sb + P2_BLO + swB3(r, bseg2));
                        bl[2 * jj][0] = r0; bl[2 * jj][1] = r2;
                        bl[2 * jj + 1][0] = r1; bl[2 * jj + 1][1] = r3;
                    }
#pragma unroll
                    for (int j = 0; j < 4; j++) {
                        mma16816(acc[j], ah, bh[j]);
                        mma16816(acc[j], ah, bl[j]);
                        mma16816(acc[j], al, bh[j]);
                    }
                }
                __syncthreads();
            }

            // write partials
            {
                const int r = wm * 16 + (lane >> 2);
#pragma unroll
                for (int j = 0; j < 4; j++) {
                    const int n = wn * 32 + 8 * j + (lane & 3) * 2;
                    zpart_self[r * 64 + n]           = acc[j][0];
                    zpart_self[r * 64 + n + 1]       = acc[j][1];
                    zpart_self[(r + 8) * 64 + n]     = acc[j][2];
                    zpart_self[(r + 8) * 64 + n + 1] = acc[j][3];
                }
            }

            // ---- per-group flag sync (release: partials visible) ----
            __threadfence();
            __syncthreads();
            if (tid == 0) {
                atomicAdd(&g_flags[g], 1u);
                const unsigned tgt = s_base + 4u * (unsigned)t;
                while ((int)(*(volatile unsigned*)&g_flags[g] - tgt) < 0)
                    __nanosleep(32);
            }
            __syncthreads();
            __threadfence();   // acquire: invalidate L1 before reading partials
        }

        // ---- pointwise (disjoint batch quarter per ks CTA) ----
        {
            float z[4];
#pragma unroll
            for (int gt = 0; gt < 4; gt++) {
                float s = xv[gt] + bb[gt];
                if (t > 0) {
                    const int n = gt * 16 + hl;
#pragma unroll
                    for (int k2 = 0; k2 < 4; k2++)
                        s += g_zpart[((size_t)(g * 4 + k2) * BATCH + pb) * 64 + n];
                }
                z[gt] = s;
            }
            float cn = sigmoidf_(z[1]) * cell + sigmoidf_(z[0]) * tanhf(z[2]);
            float hn = sigmoidf_(z[3]) * tanhf(cn);
            cell = cn;

            out[((size_t)pb * TT + t) * HH + hcol] = hn;
            __nv_bfloat16 hi = __float2bfloat16(hn);
            __nv_bfloat16 lo = __float2bfloat16(hn - __bfloat162float(hi));
            g_hhi[t & 1][pb * HH + hcol] = hi;
            g_hlo[t & 1][pb * HH + hcol] = lo;
        }

        // ---- grid parity barrier (h visibility) ----
        __threadfence();
        __syncthreads();
        if (tid == 0) {
            unsigned gen = g_bar_gen;
            if (atomicAdd(&g_bar_count, 1) == NCTA - 1) {
                g_bar_count = 0;
                __threadfence();
                g_bar_gen = gen + 1;
            } else {
                while (g_bar_gen == gen) { __nanosleep(64); }
            }
        }
        __syncthreads();
    }
}

// ============================================================================
// Launch: 5 graph nodes.
// ============================================================================
extern "C" void kernel_launch(void* const* d_in, const int* in_sizes, int n_in,
                              void* d_out, int out_size)
{
    const float* x  = (const float*)d_in[0];
    const float* Wx = (const float*)d_in[1];
    const float* Wh = (const float*)d_in[2];
    const float* b  = (const float*)d_in[3];
    float* out = (float*)d_out;

    cudaFuncSetAttribute(gemm_mma_kernel,
                         cudaFuncAttributeMaxDynamicSharedMemorySize, SMEM_DYN);
    cudaFuncSetAttribute(lstm_mma_kernel,
                         cudaFuncAttributeMaxDynamicSharedMemorySize, P2_SMEM);

    convert_x_kernel<<<(int)(((size_t)MROWS * FF / 4) / 256), 256>>>(x);
    convert_wt_kernel<<<(int)(((size_t)FF * G4) / 256), 256>>>(Wx, 0);
    convert_wt_kernel<<<(int)(((size_t)FF * G4) / 256), 256>>>(Wh, 1);

    {
        dim3 grid(G4 / 64, MROWS / 128);   // (64, 256)
        gemm_mma_kernel<<<grid, 256, SMEM_DYN>>>();
    }

    lstm_mma_kernel<<<NCTA, 256, P2_SMEM>>>(b, out);
}

// round 13
// speedup vs baseline: 2.8329x; 1.0987x over previous
#include <cuda_runtime.h>
#include <cuda_bf16.h>
#include <math.h>
#include <cstdint>

// Problem constants
#define BATCH 64
#define TT    512
#define FF    1024
#define HH    1024
#define G4    4096
#define NCTA  256           // phase-2: 64 N-groups x 4 K-splits, 2/SM co-resident
#define MROWS (BATCH * TT)

// ---------------- scratch (static device memory; no allocations) ------------
static __device__ float          g_xg[(size_t)MROWS * G4];
static __device__ __nv_bfloat16  g_xhi[(size_t)MROWS * FF];
static __device__ __nv_bfloat16  g_xlo[(size_t)MROWS * FF];
static __device__ __nv_bfloat16  g_wthi[(size_t)G4 * FF];     // WxT [n][k]
static __device__ __nv_bfloat16  g_wtlo[(size_t)G4 * FF];
static __device__ __nv_bfloat16  g_whthi[(size_t)G4 * HH];    // WhT [n][k]
static __device__ __nv_bfloat16  g_whtlo[(size_t)G4 * HH];
static __device__ __nv_bfloat16  g_hhi[2][BATCH * HH];
static __device__ __nv_bfloat16  g_hlo[2][BATCH * HH];
static __device__ float          g_zpart[NCTA * BATCH * 64];  // [g*4+ks][b][64]
static __device__ unsigned       g_flags[64];                 // per-group arrivals
static __device__ unsigned       g_bar_count;
static __device__ volatile unsigned g_bar_gen;

// ======================= PTX helpers ========================================
__device__ __forceinline__ uint32_t smem_u32(const void* p) {
    uint32_t a;
    asm("{ .reg .u64 t; cvta.to.shared.u64 t, %1; cvt.u32.u64 %0, t; }"
        : "=r"(a) : "l"(p));
    return a;
}
__device__ __forceinline__ void ldsm_x4(uint32_t& r0, uint32_t& r1,
                                        uint32_t& r2, uint32_t& r3, uint32_t addr) {
    asm volatile("ldmatrix.sync.aligned.m8n8.x4.shared.b16 {%0,%1,%2,%3}, [%4];"
                 : "=r"(r0), "=r"(r1), "=r"(r2), "=r"(r3) : "r"(addr));
}
__device__ __forceinline__ void mma16816(float* d, const uint32_t* a, const uint32_t* b) {
    asm volatile(
        "mma.sync.aligned.m16n8k16.row.col.f32.bf16.bf16.f32 "
        "{%0,%1,%2,%3}, {%4,%5,%6,%7}, {%8,%9}, {%0,%1,%2,%3};"
        : "+f"(d[0]), "+f"(d[1]), "+f"(d[2]), "+f"(d[3])
        : "r"(a[0]), "r"(a[1]), "r"(a[2]), "r"(a[3]), "r"(b[0]), "r"(b[1]));
}
// cp.async.cg: 16B global->shared, L1-BYPASS (also our cross-SM freshness tool)
__device__ __forceinline__ void cpasync16(uint32_t dst, const void* src) {
    asm volatile("cp.async.cg.shared.global [%0], [%1], 16;" :: "r"(dst), "l"(src));
}
__device__ __forceinline__ void cpcommit() { asm volatile("cp.async.commit_group;" ::: "memory"); }
template<int N> __device__ __forceinline__ void cpwait() {
    asm volatile("cp.async.wait_group %0;" :: "n"(N) : "memory");
}
// 128B-row swizzle (8 segs): used for all phase tiles
__device__ __forceinline__ uint32_t swA3(int row, int seg) {
    return (uint32_t)((row << 7) + ((seg ^ (row & 7)) << 4));
}
// phase-2 B: rows 512B (32 segs)
__device__ __forceinline__ uint32_t swB3(int n, int seg) {
    return (uint32_t)((n << 9) + ((seg ^ (n & 7)) << 4));
}

// ============================================================================
// Conversions
// ============================================================================
__global__ __launch_bounds__(256)
void convert_x_kernel(const float* __restrict__ x)
{
    size_t i = (size_t)blockIdx.x * blockDim.x + threadIdx.x;
    float4 v = ((const float4*)x)[i];
    float vv[4] = {v.x, v.y, v.z, v.w};
    __nv_bfloat16 hi[4], lo[4];
#pragma unroll
    for (int j = 0; j < 4; j++) {
        hi[j] = __float2bfloat16(vv[j]);
        lo[j] = __float2bfloat16(vv[j] - __bfloat162float(hi[j]));
    }
    __nv_bfloat162* xh = (__nv_bfloat162*)g_xhi;
    __nv_bfloat162* xl = (__nv_bfloat162*)g_xlo;
    xh[2 * i]     = __halves2bfloat162(hi[0], hi[1]);
    xh[2 * i + 1] = __halves2bfloat162(hi[2], hi[3]);
    xl[2 * i]     = __halves2bfloat162(lo[0], lo[1]);
    xl[2 * i + 1] = __halves2bfloat162(lo[2], lo[3]);
}

__global__ __launch_bounds__(256)
void convert_wt_kernel(const float* __restrict__ src, int which)
{
    __nv_bfloat16* dhi = which ? g_whthi : g_wthi;
    __nv_bfloat16* dlo = which ? g_whtlo : g_wtlo;
    size_t idx = (size_t)blockIdx.x * blockDim.x + threadIdx.x;
    int k = (int)(idx >> 12);
    int n = (int)(idx & 4095);
    float v = src[idx];
    __nv_bfloat16 hi = __float2bfloat16(v);
    __nv_bfloat16 lo = __float2bfloat16(v - __bfloat162float(hi));
    dhi[(size_t)n * FF + k] = hi;
    dlo[(size_t)n * FF + k] = lo;
}

// ============================================================================
// Phase 1: xg = x @ Wx. CTA 128x64, warp m32n32, KCHUNK=64, cp.async 2-stage.
// SMEM/buf: Ahi 16K | Alo 16K | Bhi 8K | Blo 8K = 48K; x2 bufs = 96K; 2 CTAs/SM.
// ============================================================================
#define P1_AHI 0
#define P1_ALO 16384
#define P1_BHI 32768
#define P1_BLO 40960
#define P1_BUF 49152
#define SMEM_DYN (2 * P1_BUF + 1024)
#define NCH1 16

__global__ __launch_bounds__(256, 2)
void gemm_mma_kernel()
{
    extern __shared__ char smem_raw[];
    char* smem = (char*)(((uintptr_t)smem_raw + 1023) & ~(uintptr_t)1023);
    const uint32_t sb = smem_u32(smem);

    const int tid = threadIdx.x;
    const int wid = tid >> 5;
    const int lane = tid & 31;
    const int wm = wid & 3;
    const int wn = wid >> 2;
    const int col0 = blockIdx.x * 64;
    const int row0 = blockIdx.y * 128;

    const int sr  = tid >> 3;   // 0..31
    const int ssg = tid & 7;

    float acc[2][4][4];
#pragma unroll
    for (int i = 0; i < 2; i++)
#pragma unroll
        for (int j = 0; j < 4; j++)
#pragma unroll
            for (int q = 0; q < 4; q++) acc[i][j][q] = 0.f;

    // --- stage chunk c via cp.async ---
    auto issue = [&](int c) {
        const uint32_t stg = (uint32_t)(c & 1) * P1_BUF;
        const int k0 = c * 64;
#pragma unroll
        for (int i = 0; i < 4; i++) {
            const int row = sr + 32 * i;
            const uint32_t so = swA3(row, ssg);
            const size_t src = (size_t)(row0 + row) * FF + k0 + ssg * 8;
            cpasync16(sb + stg + P1_AHI + so, g_xhi + src);
            cpasync16(sb + stg + P1_ALO + so, g_xlo + src);
        }
#pragma unroll
        for (int i = 0; i < 2; i++) {
            const int n = sr + 32 * i;
            const uint32_t so = swA3(n, ssg);
            const size_t src = (size_t)(col0 + n) * FF + k0 + ssg * 8;
            cpasync16(sb + stg + P1_BHI + so, g_wthi + src);
            cpasync16(sb + stg + P1_BLO + so, g_wtlo + src);
        }
        cpcommit();
    };

    issue(0);
    for (int c = 0; c < NCH1; c++) {
        if (c + 1 < NCH1) { issue(c + 1); cpwait<1>(); }
        else             { cpwait<0>(); }
        __syncthreads();

        const uint32_t stg = (uint32_t)(c & 1) * P1_BUF;
#pragma unroll
        for (int kk = 0; kk < 4; kk++) {
            const int lrow = lane & 15;
            const int lseg = 2 * kk + (lane >> 4);

            uint32_t ah[2][4], al[2][4];
#pragma unroll
            for (int i = 0; i < 2; i++) {
                const int r = 32 * wm + 16 * i + lrow;
                ldsm_x4(ah[i][0], ah[i][1], ah[i][2], ah[i][3],
                        sb + stg + P1_AHI + swA3(r, lseg));
                ldsm_x4(al[i][0], al[i][1], al[i][2], al[i][3],
                        sb + stg + P1_ALO + swA3(r, lseg));
            }
            uint32_t bh[4][2], bl[4][2];
#pragma unroll
            for (int jj = 0; jj < 2; jj++) {
                const int r = 32 * wn + 16 * jj + lrow;
                uint32_t r0, r1, r2, r3;
                ldsm_x4(r0, r1, r2, r3, sb + stg + P1_BHI + swA3(r, lseg));
                bh[2 * jj][0] = r0; bh[2 * jj][1] = r2;
                bh[2 * jj + 1][0] = r1; bh[2 * jj + 1][1] = r3;
                ldsm_x4(r0, r1, r2, r3, sb + stg + P1_BLO + swA3(r, lseg));
                bl[2 * jj][0] = r0; bl[2 * jj][1] = r2;
                bl[2 * jj + 1][0] = r1; bl[2 * jj + 1][1] = r3;
            }
#pragma unroll
            for (int i = 0; i < 2; i++)
#pragma unroll
                for (int j = 0; j < 4; j++) {
                    mma16816(acc[i][j], ah[i], bh[j]);
                    mma16816(acc[i][j], ah[i], bl[j]);
                    mma16816(acc[i][j], al[i], bh[j]);
                }
        }
        __syncthreads();
    }

    const int tq = lane >> 2;
    const int tr = lane & 3;
#pragma unroll
    for (int i = 0; i < 2; i++) {
        const int mbase = row0 + 32 * wm + 16 * i;
#pragma unroll
        for (int j = 0; j < 4; j++) {
            const int nbase = col0 + 32 * wn + 8 * j;
            float* p0 = &g_xg[(size_t)(mbase + tq) * G4 + nbase + 2 * tr];
            float* p1 = &g_xg[(size_t)(mbase + tq + 8) * G4 + nbase + 2 * tr];
            p0[0] = acc[i][j][0]; p0[1] = acc[i][j][1];
            p1[0] = acc[i][j][2]; p1[1] = acc[i][j][3];
        }
    }
}

// ============================================================================
// Phase 2: persistent K-split recurrence (validated R12), with
// cp.async.cg A-staging (L1 bypass -> no acquire fences) and __ldcv partials.
// ============================================================================
#define P2_BHI   0
#define P2_BLO   32768
#define P2_A     65536
#define P2_ABUF  16384
#define P2_SMEM  (65536 + 32768 + 1024)

__device__ __forceinline__ float sigmoidf_(float v) { return 1.f / (1.f + expf(-v)); }

__global__ __launch_bounds__(256, 2)
void lstm_mma_kernel(const float* __restrict__ bias, float* __restrict__ out)
{
    extern __shared__ char smem_raw[];
    char* smem = (char*)(((uintptr_t)smem_raw + 1023) & ~(uintptr_t)1023);
    const uint32_t sb = smem_u32(smem);

    const int tid  = threadIdx.x;
    const int wid  = tid >> 5;
    const int lane = tid & 31;
    const int wm   = wid & 3;
    const int wn   = wid >> 2;
    const int g    = blockIdx.x >> 2;
    const int ks   = blockIdx.x & 3;
    const int kbase = ks * 256;

    __shared__ unsigned s_base;

    const int pb = ks * 16 + (tid >> 4);
    const int hl = tid & 15;
    const int hcol = g * 16 + hl;
    float bb[4];
#pragma unroll
    for (int gt = 0; gt < 4; gt++) bb[gt] = bias[gt * 1024 + hcol];
    float cell = 0.f;

    // ---- resident B: 64 n x 256 k slice, hi/lo ----
#pragma unroll
    for (int i = 0; i < 8; i++) {
        int fi  = tid + i * 256;
        int n   = fi >> 5;
        int seg = fi & 31;
        int gn  = (n >> 4) * 1024 + g * 16 + (n & 15);
        uint32_t so = swB3(n, seg);
        const size_t src = (size_t)gn * HH + kbase + seg * 8;
        *(float4*)(smem + P2_BHI + so) = *(const float4*)(g_whthi + src);
        *(float4*)(smem + P2_BLO + so) = *(const float4*)(g_whtlo + src);
    }
    __syncthreads();

    const int ar  = tid >> 3;   // 0..31
    const int asg = tid & 7;

    float* zpart_self = g_zpart + (size_t)(g * 4 + ks) * BATCH * 64;

    for (int t = 0; t < TT; t++) {
        if (t == 0 && tid == 0) s_base = g_flags[g];

        float xv[4];
#pragma unroll
        for (int gt = 0; gt < 4; gt++)
            xv[gt] = g_xg[((size_t)pb * TT + t) * G4 + gt * 1024 + hcol];

        if (t > 0) {
            const __nv_bfloat16* hh = g_hhi[(t - 1) & 1];
            const __nv_bfloat16* hl_ = g_hlo[(t - 1) & 1];

            float acc[4][4];
#pragma unroll
            for (int j = 0; j < 4; j++)
#pragma unroll
                for (int q = 0; q < 4; q++) acc[j][q] = 0.f;

            // stage A chunk via cp.async.cg (L1 bypass => fresh h, no fence)
            auto issueA = [&](int kc) {
                const uint32_t abase = P2_A + (uint32_t)(kc & 1) * P2_ABUF;
                const int kn = kbase + kc * 64;
#pragma unroll
                for (int i = 0; i < 2; i++) {
                    const int row = ar + 32 * i;
                    const uint32_t so = swA3(row, asg);
                    const size_t off = (size_t)row * HH + kn + asg * 8;
                    cpasync16(sb + abase + so,        hh  + off);
                    cpasync16(sb + abase + 8192 + so, hl_ + off);
                }
                cpcommit();
            };

            issueA(0);
            for (int kc = 0; kc < 4; kc++) {
                if (kc + 1 < 4) { issueA(kc + 1); cpwait<1>(); }
                else            { cpwait<0>(); }
                __syncthreads();

                const uint32_t abase = P2_A + (uint32_t)(kc & 1) * P2_ABUF;
#pragma unroll
                for (int kk = 0; kk < 4; kk++) {
                    const int lrow = lane & 15;
                    const int hs   = lane >> 4;
                    const int aseg2 = 2 * kk + hs;
                    const int bseg2 = 2 * (kc * 4 + kk) + hs;

                    uint32_t ah[4], al[4];
                    ldsm_x4(ah[0], ah[1], ah[2], ah[3],
                            sb + abase + swA3(wm * 16 + lrow, aseg2));
                    ldsm_x4(al[0], al[1], al[2], al[3],
                            sb + abase + 8192 + swA3(wm * 16 + lrow, aseg2));

                    uint32_t bh[4][2], bl[4][2];
#pragma unroll
                    for (int jj = 0; jj < 2; jj++) {
                        const int r = wn * 32 + 16 * jj + lrow;
                        uint32_t r0, r1, r2, r3;
                        ldsm_x4(r0, r1, r2, r3, sb + P2_BHI + swB3(r, bseg2));
                        bh[2 * jj][0] = r0; bh[2 * jj][1] = r2;
                        bh[2 * jj + 1][0] = r1; bh[2 * jj + 1][1] = r3;
                        ldsm_x4(r0, r1, r2, r3, sb + P2_BLO + swB3(r, bseg2));
                        bl[2 * jj][0] = r0; bl[2 * jj][1] = r2;
                        bl[2 * jj + 1][0] = r1; bl[2 * jj + 1][1] = r3;
                    }
#pragma unroll
                    for (int j = 0; j < 4; j++) {
                        mma16816(acc[j], ah, bh[j]);
                        mma16816(acc[j], ah, bl[j]);
                        mma16816(acc[j], al, bh[j]);
                    }
                }
                __syncthreads();
            }

            // write partials
            {
                const int r = wm * 16 + (lane >> 2);
#pragma unroll
                for (int j = 0; j < 4; j++) {
                    const int n = wn * 32 + 8 * j + (lane & 3) * 2;
                    zpart_self[r * 64 + n]           = acc[j][0];
                    zpart_self[r * 64 + n + 1]       = acc[j][1];
                    zpart_self[(r + 8) * 64 + n]     = acc[j][2];
                    zpart_self[(r + 8) * 64 + n + 1] = acc[j][3];
                }
            }

            // per-group flag sync (release only; consumers use __ldcv)
            __threadfence();
            __syncthreads();
            if (tid == 0) {
                atomicAdd(&g_flags[g], 1u);
                const unsigned tgt = s_base + 4u * (unsigned)t;
                while ((int)(*(volatile unsigned*)&g_flags[g] - tgt) < 0)
                    __nanosleep(32);
            }
            __syncthreads();
        }

        // ---- pointwise (zpart read via __ldcv: L2-fresh, no acquire fence) ----
        {
            float z[4];
#pragma unroll
            for (int gt = 0; gt < 4; gt++) {
                float s = xv[gt] + bb[gt];
                if (t > 0) {
                    const int n = gt * 16 + hl;
#pragma unroll
                    for (int k2 = 0; k2 < 4; k2++)
                        s += __ldcv(&g_zpart[((size_t)(g * 4 + k2) * BATCH + pb) * 64 + n]);
                }
                z[gt] = s;
            }
            float cn = sigmoidf_(z[1]) * cell + sigmoidf_(z[0]) * tanhf(z[2]);
            float hn = sigmoidf_(z[3]) * tanhf(cn);
            cell = cn;

            out[((size_t)pb * TT + t) * HH + hcol] = hn;
            __nv_bfloat16 hi = __float2bfloat16(hn);
            __nv_bfloat16 lo = __float2bfloat16(hn - __bfloat162float(hi));
            g_hhi[t & 1][pb * HH + hcol] = hi;
            g_hlo[t & 1][pb * HH + hcol] = lo;
        }

        // ---- grid parity barrier (h visibility; release fence kept) ----
        __threadfence();
        __syncthreads();
        if (tid == 0) {
            unsigned gen = g_bar_gen;
            if (atomicAdd(&g_bar_count, 1) == NCTA - 1) {
                g_bar_count = 0;
                __threadfence();
                g_bar_gen = gen + 1;
            } else {
                while (g_bar_gen == gen) { __nanosleep(32); }
            }
        }
        __syncthreads();
    }
}

// ============================================================================
// Launch: 5 graph nodes.
// ============================================================================
extern "C" void kernel_launch(void* const* d_in, const int* in_sizes, int n_in,
                              void* d_out, int out_size)
{
    const float* x  = (const float*)d_in[0];
    const float* Wx = (const float*)d_in[1];
    const float* Wh = (const float*)d_in[2];
    const float* b  = (const float*)d_in[3];
    float* out = (float*)d_out;

    cudaFuncSetAttribute(gemm_mma_kernel,
                         cudaFuncAttributeMaxDynamicSharedMemorySize, SMEM_DYN);
    cudaFuncSetAttribute(lstm_mma_kernel,
                         cudaFuncAttributeMaxDynamicSharedMemorySize, P2_SMEM);

    convert_x_kernel<<<(int)(((size_t)MROWS * FF / 4) / 256), 256>>>(x);
    convert_wt_kernel<<<(int)(((size_t)FF * G4) / 256), 256>>>(Wx, 0);
    convert_wt_kernel<<<(int)(((size_t)FF * G4) / 256), 256>>>(Wh, 1);

    {
        dim3 grid(G4 / 64, MROWS / 128);   // (64, 256)
        gemm_mma_kernel<<<grid, 256, SMEM_DYN>>>();
    }

    lstm_mma_kernel<<<NCTA, 256, P2_SMEM>>>(b, out);
}